// round 4
// baseline (speedup 1.0000x reference)
#include <cuda_runtime.h>
#include <cuda_bf16.h>
#include <cstdint>

// ---------------- problem constants ----------------
#define DMODEL 2048
#define DSTATE 16
#define DTRANK 128
#define BSZ    2
#define SEQ    1024
#define MROWS  (BSZ*SEQ)            // 2048
#define XDBL_W (DTRANK + 2*DSTATE)  // 160
#define K3     (3*DMODEL)           // 6144
#define K3DT   (3*DTRANK)           // 384
#define NSPLITK 4
#define XP_LD   256                 // padded xproj slab width

// ---------------- static scratch ----------------
__device__ float g_xz  [(size_t)MROWS * (2*DMODEL)];
__device__ float g_u   [(size_t)MROWS * DMODEL];
__device__ float g_xdbl[(size_t)MROWS * XDBL_W];
__device__ float g_dt  [(size_t)MROWS * DMODEL];
__device__ float g_part[(size_t)NSPLITK * MROWS * XP_LD];

__device__ __nv_bfloat16 g_xh3 [(size_t)MROWS  * K3];
__device__ __nv_bfloat16 g_wih3[(size_t)(2*DMODEL) * K3];
__device__ __nv_bfloat16 g_uh3 [(size_t)MROWS  * K3];
__device__ __nv_bfloat16 g_wxh3[(size_t)XDBL_W * K3];
__device__ __nv_bfloat16 g_dta3[(size_t)MROWS  * K3DT];
__device__ __nv_bfloat16 g_wdt3[(size_t)DMODEL * K3DT];
__device__ __nv_bfloat16 g_yph3[(size_t)MROWS  * K3];
__device__ __nv_bfloat16 g_woh3[(size_t)DMODEL * K3];

// ---------------- PTX helpers (non-'a' features only) ----------------
__device__ __forceinline__ uint32_t smem_u32(const void* p) {
    uint32_t a;
    asm("{ .reg .u64 t; cvta.to.shared.u64 t, %1; cvt.u32.u64 %0, t; }" : "=r"(a) : "l"(p));
    return a;
}
__device__ __forceinline__ void cp_async16(uint32_t saddr, const void* gaddr, int src_bytes) {
    asm volatile("cp.async.cg.shared.global [%0], [%1], 16, %2;"
                 :: "r"(saddr), "l"(gaddr), "r"(src_bytes) : "memory");
}
#define CP_COMMIT() asm volatile("cp.async.commit_group;" ::: "memory")
#define CP_WAIT1()  asm volatile("cp.async.wait_group 1;" ::: "memory")

__device__ __forceinline__ void ldsm_x4(uint32_t* r, uint32_t addr) {
    asm volatile("ldmatrix.sync.aligned.m8n8.x4.shared.b16 {%0,%1,%2,%3}, [%4];"
                 : "=r"(r[0]), "=r"(r[1]), "=r"(r[2]), "=r"(r[3]) : "r"(addr));
}
__device__ __forceinline__ void mma16816(float* d, const uint32_t* a, const uint32_t* b) {
    asm volatile(
        "mma.sync.aligned.m16n8k16.row.col.f32.bf16.bf16.f32 "
        "{%0,%1,%2,%3}, {%4,%5,%6,%7}, {%8,%9}, {%0,%1,%2,%3};"
        : "+f"(d[0]), "+f"(d[1]), "+f"(d[2]), "+f"(d[3])
        : "r"(a[0]), "r"(a[1]), "r"(a[2]), "r"(a[3]), "r"(b[0]), "r"(b[1]));
}

// split helpers
__device__ __forceinline__ void split2(float v, __nv_bfloat16& h, __nv_bfloat16& l) {
    h = __float2bfloat16(v);
    l = __float2bfloat16(v - __bfloat162float(h));
}

// ---------------- bf16x3 split kernels (for fp32 inputs/weights) ----------
// ASIDE=1: [hi,hi,lo]; ASIDE=0: [hi,lo,hi].
template<int ASIDE>
__global__ void __launch_bounds__(256)
split3_kernel(const float* __restrict__ src, int ld, int cols,
              __nv_bfloat16* __restrict__ dst, int total)
{
    int idx = blockIdx.x * blockDim.x + threadIdx.x;
    if (idx >= total) return;
    int halfc = cols >> 1;
    int r = idx / halfc;
    int c = idx - r * halfc;
    float v0 = src[(size_t)r * ld + 2*c];
    float v1 = src[(size_t)r * ld + 2*c + 1];
    __nv_bfloat16 h0, l0, h1, l1;
    split2(v0, h0, l0); split2(v1, h1, l1);
    __nv_bfloat162* out = (__nv_bfloat162*)(dst + (size_t)r * 3 * cols + 6*c);
    __nv_bfloat162 w0, w1, w2;
    if (ASIDE) { w0.x=h0; w0.y=h0; w1.x=l0; w1.y=h1; w2.x=h1; w2.y=l1; }
    else       { w0.x=h0; w0.y=l0; w1.x=h0; w1.y=h1; w2.x=l1; w2.y=h1; }
    out[0] = w0; out[1] = w1; out[2] = w2;
}

// ---------------- bf16 tensor-core GEMM (mma.sync) -------------------------
// C[m,n] += sum over K segment of A[m,k]*B[n,k]; A:[*,Kstride], B:[Nb,Kstride]
// CTA tile 128x256, 8 warps each 64x64, BK=64, 3-stage cp.async.
// grid.z = split-K index (K segment Klen, C += z*cslab).
// EPI==1: softplus(acc + bias[n]).
#define STG   49152          // stage stride: A 16KB + B 32KB
#define GSMEM (3*STG)

template<int EPI>
__global__ void __launch_bounds__(256, 1)
gemm_mma(const __nv_bfloat16* __restrict__ A,
         const __nv_bfloat16* __restrict__ B,
         float* __restrict__ C, int ldc,
         int Nb, int Kstride, int Klen, size_t cslab,
         const float* __restrict__ bias)
{
    extern __shared__ __align__(1024) char smem[];
    const uint32_t sbase = smem_u32(smem);

    const int tid  = threadIdx.x;
    const int wid  = tid >> 5;
    const int lane = tid & 31;
    const int m0 = blockIdx.y << 7;
    const int n0 = blockIdx.x << 8;
    const int koff = blockIdx.z * Klen;
    C += (size_t)blockIdx.z * cslab;

    const int wm = (wid & 1) * 64;
    const int wn = (wid >> 1) * 64;
    const int nch = Klen >> 6;

    const int lrow = tid >> 3;
    const int lch  = tid & 7;

    auto load_stage = [&](int s, int i) {
        const int k0 = koff + (i << 6);
        const uint32_t sA = sbase + s * STG;
        const uint32_t sB = sA + 16384;
        // A: 128 rows x 8 chunks = 1024
#pragma unroll
        for (int j = 0; j < 4; j++) {
            int e = tid + j * 256;
            int row = e >> 3, ch = e & 7;
            uint32_t so = (uint32_t)(row * 128 + ((ch ^ (row & 7)) << 4));
            cp_async16(sA + so, A + (size_t)(m0 + row) * Kstride + k0 + ch * 8, 16);
        }
        // B: 256 rows x 8 chunks = 2048
#pragma unroll
        for (int j = 0; j < 8; j++) {
            int e = tid + j * 256;
            int row = e >> 3, ch = e & 7;
            uint32_t so = (uint32_t)(row * 128 + ((ch ^ (row & 7)) << 4));
            int n = n0 + row;
            int nc = (n < Nb) ? n : (Nb - 1);
            cp_async16(sB + so, B + (size_t)nc * Kstride + k0 + ch * 8,
                       (n < Nb) ? 16 : 0);
        }
    };

    float acc[4][8][4];
#pragma unroll
    for (int i = 0; i < 4; i++)
#pragma unroll
        for (int j = 0; j < 8; j++)
#pragma unroll
            for (int e = 0; e < 4; e++) acc[i][j][e] = 0.f;

    const int a_r = lane & 15;
    const int a_c = lane >> 4;
    const int b_r = ((lane >> 4) & 1) * 8 + (lane & 7);
    const int b_c = (lane >> 3) & 1;

    load_stage(0, 0); CP_COMMIT();
    load_stage(1, 1); CP_COMMIT();

    for (int i = 0; i < nch; i++) {
        CP_WAIT1();
        __syncthreads();
        if (i + 2 < nch) load_stage((i + 2) % 3, i + 2);
        CP_COMMIT();

        const uint32_t sA = sbase + (i % 3) * STG;
        const uint32_t sB = sA + 16384;
#pragma unroll
        for (int ks = 0; ks < 4; ks++) {
            uint32_t af[4][4], bf4[4][4];
#pragma unroll
            for (int mi = 0; mi < 4; mi++) {
                int row = wm + mi * 16 + a_r;
                int ch  = ks * 2 + a_c;
                ldsm_x4(af[mi], sA + row * 128 + ((ch ^ (row & 7)) << 4));
            }
#pragma unroll
            for (int nj = 0; nj < 4; nj++) {
                int row = wn + nj * 16 + b_r;
                int ch  = ks * 2 + b_c;
                ldsm_x4(bf4[nj], sB + row * 128 + ((ch ^ (row & 7)) << 4));
            }
#pragma unroll
            for (int mi = 0; mi < 4; mi++)
#pragma unroll
                for (int ni = 0; ni < 8; ni++)
                    mma16816(acc[mi][ni], af[mi], &bf4[ni >> 1][(ni & 1) * 2]);
        }
    }

    // epilogue
    const int er = lane >> 2;
    const int ec = (lane & 3) * 2;
#pragma unroll
    for (int mi = 0; mi < 4; mi++) {
#pragma unroll
        for (int half = 0; half < 2; half++) {
            int m = m0 + wm + mi * 16 + er + half * 8;
            float* crow = C + (size_t)m * ldc;
#pragma unroll
            for (int ni = 0; ni < 8; ni++) {
                int n = n0 + wn + ni * 8 + ec;
                float v0 = acc[mi][ni][half * 2 + 0];
                float v1 = acc[mi][ni][half * 2 + 1];
                if (EPI == 1) {
                    v0 += bias[n];     v1 += bias[n + 1];
                    v0 = (v0 > 20.f) ? v0 : log1pf(expf(v0));
                    v1 = (v1 > 20.f) ? v1 : log1pf(expf(v1));
                }
                *(float2*)&crow[n] = make_float2(v0, v1);
            }
        }
    }
}

// ---------------- xproj split-K reduce: xdbl fp32 + fused dt-rank split ----
__global__ void __launch_bounds__(256)
reduce_xproj(const float* __restrict__ part,
             float* __restrict__ xdbl,
             __nv_bfloat16* __restrict__ dta3)
{
    int idx = blockIdx.x * blockDim.x + threadIdx.x;
    if (idx >= MROWS * XDBL_W) return;
    int m = idx / XDBL_W;
    int n = idx - m * XDBL_W;
    float s = 0.f;
#pragma unroll
    for (int z = 0; z < NSPLITK; z++)
        s += part[(size_t)z * MROWS * XP_LD + (size_t)m * XP_LD + n];
    xdbl[idx] = s;
    if (n < DTRANK) {
        __nv_bfloat16 h, l; split2(s, h, l);
        __nv_bfloat16* o = dta3 + (size_t)m * K3DT + 3 * n;
        o[0] = h; o[1] = h; o[2] = l;
    }
}

// ---------------- conv(K=4) + SiLU + fused A-side split --------------------
__global__ void __launch_bounds__(256)
conv_silu_split(const float* __restrict__ xz,
                const float* __restrict__ conv_w,
                const float* __restrict__ conv_b,
                float* __restrict__ u,
                __nv_bfloat16* __restrict__ uh3)
{
    int idx = blockIdx.x * blockDim.x + threadIdx.x;
    if (idx >= MROWS * DMODEL) return;
    int d = idx & (DMODEL - 1);
    int m = idx >> 11;
    int l = m & (SEQ - 1);
    int b = m >> 10;

    float w0 = conv_w[d*4+0], w1 = conv_w[d*4+1],
          w2 = conv_w[d*4+2], w3 = conv_w[d*4+3];
    float acc = conv_b[d];
    size_t base = (size_t)(b * SEQ) * (2*DMODEL) + d;
    if (l >= 3) acc += w0 * xz[base + (size_t)(l-3) * (2*DMODEL)];
    if (l >= 2) acc += w1 * xz[base + (size_t)(l-2) * (2*DMODEL)];
    if (l >= 1) acc += w2 * xz[base + (size_t)(l-1) * (2*DMODEL)];
    acc += w3 * xz[base + (size_t)l * (2*DMODEL)];
    float sig = 1.f / (1.f + expf(-acc));
    float val = acc * sig;
    u[idx] = val;
    __nv_bfloat16 h, lo; split2(val, h, lo);
    __nv_bfloat16* o = uh3 + (size_t)m * K3 + 3 * d;
    o[0] = h; o[1] = h; o[2] = lo;
}

// ---------------- selective scan + gate + fused A-side split ---------------
#define DG 16
#define CL 64
__global__ void __launch_bounds__(256)
scan_kernel(const float* __restrict__ xdbl,
            const float* __restrict__ dt,
            const float* __restrict__ u,
            const float* __restrict__ xz,
            const float* __restrict__ A_log,
            const float* __restrict__ Dskip,
            __nv_bfloat16* __restrict__ yph3)
{
    const int b    = blockIdx.x >> 7;
    const int dblk = blockIdx.x & 127;
    const int d0   = dblk * DG;
    const int tid  = threadIdx.x;
    const int dloc = tid >> 4;
    const int n    = tid & 15;
    const int d    = d0 + dloc;

    const float Adn = -expf(A_log[d * DSTATE + n]);
    const float Dsk = Dskip[d];
    float h = 0.f;

    __shared__ float sdt[CL*DG], su[CL*DG], sz[CL*DG];
    __shared__ float sB[CL*DSTATE], sC[CL*DSTATE];

    for (int c = 0; c < SEQ / CL; c++) {
        const int l0 = c * CL;
        __syncthreads();
#pragma unroll
        for (int e = tid; e < CL*DG; e += 256) {
            int lr = e >> 4, el = e & 15;
            size_t row = (size_t)(b * SEQ + l0 + lr);
            sdt[e] = dt[row * DMODEL + d0 + el];
            su[e]  = u [row * DMODEL + d0 + el];
            sz[e]  = xz[row * (2*DMODEL) + DMODEL + d0 + el];
            sB[e]  = xdbl[row * XDBL_W + DTRANK + el];
            sC[e]  = xdbl[row * XDBL_W + DTRANK + DSTATE + el];
        }
        __syncthreads();

#pragma unroll 4
        for (int lr = 0; lr < CL; lr++) {
            float dtv = sdt[lr*16 + dloc];
            float uu  = su [lr*16 + dloc];
            float dA  = __expf(dtv * Adn);
            h = dA * h + (dtv * uu) * sB[lr*16 + n];
            float y = h * sC[lr*16 + n];
            y += __shfl_xor_sync(0xffffffffu, y, 8, 16);
            y += __shfl_xor_sync(0xffffffffu, y, 4, 16);
            y += __shfl_xor_sync(0xffffffffu, y, 2, 16);
            y += __shfl_xor_sync(0xffffffffu, y, 1, 16);
            if (n == 0) {
                float z   = sz[lr*16 + dloc];
                float sig = 1.f / (1.f + __expf(-z));
                float val = (y + uu * Dsk) * (z * sig);
                __nv_bfloat16 hh, ll; split2(val, hh, ll);
                __nv_bfloat16* o = yph3 +
                    (size_t)(b * SEQ + l0 + lr) * K3 + 3 * d;
                o[0] = hh; o[1] = hh; o[2] = ll;
            }
        }
    }
}

// ---------------- launch ----------------
extern "C" void kernel_launch(void* const* d_in, const int* in_sizes, int n_in,
                              void* d_out, int out_size)
{
    const float* x      = (const float*)d_in[0];
    const float* W_in   = (const float*)d_in[1];
    const float* conv_w = (const float*)d_in[2];
    const float* conv_b = (const float*)d_in[3];
    const float* W_xproj= (const float*)d_in[4];
    const float* W_dt   = (const float*)d_in[5];
    const float* b_dt   = (const float*)d_in[6];
    const float* A_log  = (const float*)d_in[7];
    const float* Dskip  = (const float*)d_in[8];
    const float* W_out  = (const float*)d_in[9];
    float* out = (float*)d_out;

    float *xz, *u, *xdbl, *dtb, *part;
    __nv_bfloat16 *xh3, *wih3, *uh3, *wxh3, *dta3, *wdt3, *yph3, *woh3;
    cudaGetSymbolAddress((void**)&xz,   g_xz);
    cudaGetSymbolAddress((void**)&u,    g_u);
    cudaGetSymbolAddress((void**)&xdbl, g_xdbl);
    cudaGetSymbolAddress((void**)&dtb,  g_dt);
    cudaGetSymbolAddress((void**)&part, g_part);
    cudaGetSymbolAddress((void**)&xh3,  g_xh3);
    cudaGetSymbolAddress((void**)&wih3, g_wih3);
    cudaGetSymbolAddress((void**)&uh3,  g_uh3);
    cudaGetSymbolAddress((void**)&wxh3, g_wxh3);
    cudaGetSymbolAddress((void**)&dta3, g_dta3);
    cudaGetSymbolAddress((void**)&wdt3, g_wdt3);
    cudaGetSymbolAddress((void**)&yph3, g_yph3);
    cudaGetSymbolAddress((void**)&woh3, g_woh3);

    cudaFuncSetAttribute(gemm_mma<0>, cudaFuncAttributeMaxDynamicSharedMemorySize, GSMEM);
    cudaFuncSetAttribute(gemm_mma<1>, cudaFuncAttributeMaxDynamicSharedMemorySize, GSMEM);

    // --- 1) split x, W_in; xz = x @ W_in^T ---
    {
        int tot = MROWS * DMODEL / 2;
        split3_kernel<1><<<(tot+255)/256, 256>>>(x, DMODEL, DMODEL, xh3, tot);
        int totw = (2*DMODEL) * DMODEL / 2;
        split3_kernel<0><<<(totw+255)/256, 256>>>(W_in, DMODEL, DMODEL, wih3, totw);
        dim3 grid((2*DMODEL)/256, MROWS/128, 1);
        gemm_mma<0><<<grid, 256, GSMEM>>>(xh3, wih3, xz, 2*DMODEL,
                                          2*DMODEL, K3, K3, 0, nullptr);
    }
    // --- 2) u = silu(conv(xz[:, :2048])), fused bf16x3 split ---
    {
        int total = MROWS * DMODEL;
        conv_silu_split<<<(total+255)/256, 256>>>(xz, conv_w, conv_b, u, uh3);
    }
    // --- 3) x_dbl = u @ W_xproj^T  (split-K x4 -> reduce, fused dt split) ---
    {
        int totw = XDBL_W * DMODEL / 2;
        split3_kernel<0><<<(totw+255)/256, 256>>>(W_xproj, DMODEL, DMODEL, wxh3, totw);
        dim3 grid(1, MROWS/128, NSPLITK);
        gemm_mma<0><<<grid, 256, GSMEM>>>(uh3, wxh3, part, XP_LD,
                                          XDBL_W, K3, K3/NSPLITK,
                                          (size_t)MROWS * XP_LD, nullptr);
        int tot = MROWS * XDBL_W;
        reduce_xproj<<<(tot+255)/256, 256>>>(part, xdbl, dta3);
    }
    // --- 4) dt = softplus(x_dbl[:, :128] @ W_dt^T + b_dt) ---
    {
        int totw = DMODEL * DTRANK / 2;
        split3_kernel<0><<<(totw+255)/256, 256>>>(W_dt, DTRANK, DTRANK, wdt3, totw);
        dim3 grid(DMODEL/256, MROWS/128, 1);
        gemm_mma<1><<<grid, 256, GSMEM>>>(dta3, wdt3, dtb, DMODEL,
                                          DMODEL, K3DT, K3DT, 0, b_dt);
    }
    // --- 5) selective scan + gate, fused bf16x3 split ---
    scan_kernel<<<BSZ * (DMODEL/DG), 256>>>(xdbl, dtb, u, xz, A_log, Dskip, yph3);
    // --- 6) out = ypre @ W_out^T ---
    {
        int totw = DMODEL * DMODEL / 2;
        split3_kernel<0><<<(totw+255)/256, 256>>>(W_out, DMODEL, DMODEL, woh3, totw);
        dim3 grid(DMODEL/256, MROWS/128, 1);
        gemm_mma<0><<<grid, 256, GSMEM>>>(yph3, woh3, out, DMODEL,
                                          DMODEL, K3, K3, 0, nullptr);
    }
}

// round 5
// speedup vs baseline: 1.0709x; 1.0709x over previous
#include <cuda_runtime.h>
#include <cuda_bf16.h>
#include <cstdint>

// ---------------- problem constants ----------------
#define DMODEL 2048
#define DSTATE 16
#define DTRANK 128
#define BSZ    2
#define SEQ    1024
#define MROWS  (BSZ*SEQ)            // 2048
#define XDBL_W (DTRANK + 2*DSTATE)  // 160
#define K3     (3*DMODEL)           // 6144
#define K3DT   (3*DTRANK)           // 384
#define NSPLITK 4
#define XP_LD   256

// ---------------- static scratch ----------------
__device__ float g_xz  [(size_t)MROWS * (2*DMODEL)];
__device__ float g_u   [(size_t)MROWS * DMODEL];
__device__ float g_xdbl[(size_t)MROWS * XDBL_W];
__device__ float g_dt  [(size_t)MROWS * DMODEL];
__device__ float g_part[(size_t)NSPLITK * MROWS * XP_LD];

__device__ __nv_bfloat16 g_xh3 [(size_t)MROWS  * K3];
__device__ __nv_bfloat16 g_wih3[(size_t)(2*DMODEL) * K3];
__device__ __nv_bfloat16 g_uh3 [(size_t)MROWS  * K3];
__device__ __nv_bfloat16 g_wxh3[(size_t)XDBL_W * K3];
__device__ __nv_bfloat16 g_dta3[(size_t)MROWS  * K3DT];
__device__ __nv_bfloat16 g_wdt3[(size_t)DMODEL * K3DT];
__device__ __nv_bfloat16 g_yph3[(size_t)MROWS  * K3];
__device__ __nv_bfloat16 g_woh3[(size_t)DMODEL * K3];

// ---------------- PTX helpers ----------------
__device__ __forceinline__ uint32_t smem_u32(const void* p) {
    uint32_t a;
    asm("{ .reg .u64 t; cvta.to.shared.u64 t, %1; cvt.u32.u64 %0, t; }" : "=r"(a) : "l"(p));
    return a;
}
__device__ __forceinline__ void cp_async16(uint32_t saddr, const void* gaddr, int src_bytes) {
    asm volatile("cp.async.cg.shared.global [%0], [%1], 16, %2;"
                 :: "r"(saddr), "l"(gaddr), "r"(src_bytes) : "memory");
}
#define CP_COMMIT() asm volatile("cp.async.commit_group;" ::: "memory")
#define CP_WAIT1()  asm volatile("cp.async.wait_group 1;" ::: "memory")

__device__ __forceinline__ void ldsm_x4(uint32_t* r, uint32_t addr) {
    asm volatile("ldmatrix.sync.aligned.m8n8.x4.shared.b16 {%0,%1,%2,%3}, [%4];"
                 : "=r"(r[0]), "=r"(r[1]), "=r"(r[2]), "=r"(r[3]) : "r"(addr));
}
__device__ __forceinline__ void mma16816(float* d, const uint32_t* a, const uint32_t* b) {
    asm volatile(
        "mma.sync.aligned.m16n8k16.row.col.f32.bf16.bf16.f32 "
        "{%0,%1,%2,%3}, {%4,%5,%6,%7}, {%8,%9}, {%0,%1,%2,%3};"
        : "+f"(d[0]), "+f"(d[1]), "+f"(d[2]), "+f"(d[3])
        : "r"(a[0]), "r"(a[1]), "r"(a[2]), "r"(a[3]), "r"(b[0]), "r"(b[1]));
}
__device__ __forceinline__ void split2(float v, __nv_bfloat16& h, __nv_bfloat16& l) {
    h = __float2bfloat16(v);
    l = __float2bfloat16(v - __bfloat162float(h));
}

// ---------------- bf16x3 split kernels ----------------
template<int ASIDE>
__global__ void __launch_bounds__(256)
split3_kernel(const float* __restrict__ src, int ld, int cols,
              __nv_bfloat16* __restrict__ dst, int total)
{
    int idx = blockIdx.x * blockDim.x + threadIdx.x;
    if (idx >= total) return;
    int halfc = cols >> 1;
    int r = idx / halfc;
    int c = idx - r * halfc;
    float v0 = src[(size_t)r * ld + 2*c];
    float v1 = src[(size_t)r * ld + 2*c + 1];
    __nv_bfloat16 h0, l0, h1, l1;
    split2(v0, h0, l0); split2(v1, h1, l1);
    __nv_bfloat162* out = (__nv_bfloat162*)(dst + (size_t)r * 3 * cols + 6*c);
    __nv_bfloat162 w0, w1, w2;
    if (ASIDE) { w0.x=h0; w0.y=h0; w1.x=l0; w1.y=h1; w2.x=h1; w2.y=l1; }
    else       { w0.x=h0; w0.y=l0; w1.x=h0; w1.y=h1; w2.x=l1; w2.y=h1; }
    out[0] = w0; out[1] = w1; out[2] = w2;
}

// ---------------- bf16 tensor-core GEMM (round-3 geometry) -----------------
// C[m,n] (+slab z) = sum_{k in segment} A[m,k]*B[n,k]
// CTA 128x128, 8 warps each 64x32, BK=64, 2-stage cp.async double buffer.
// EPI==1: softplus(acc + bias[n]).
#define GSMEM (2*32768)

template<int EPI>
__global__ void __launch_bounds__(256, 2)
gemm_mma(const __nv_bfloat16* __restrict__ A,
         const __nv_bfloat16* __restrict__ B,
         float* __restrict__ C, int ldc,
         int Nb, int Kstride, int Klen, size_t cslab,
         const float* __restrict__ bias)
{
    extern __shared__ __align__(1024) char smem[];
    const uint32_t sbase = smem_u32(smem);

    const int tid  = threadIdx.x;
    const int wid  = tid >> 5;
    const int lane = tid & 31;
    const int m0 = blockIdx.y << 7;
    const int n0 = blockIdx.x << 7;
    const int koff = blockIdx.z * Klen;
    C += (size_t)blockIdx.z * cslab;

    const int wm = (wid & 1) * 64;
    const int wn = (wid >> 1) * 32;
    const int nch = Klen >> 6;

    const int lrow = tid >> 3;
    const int lch  = tid & 7;
    auto load_stage = [&](int s, int i) {
        const int k0 = koff + (i << 6);
        const uint32_t sA = sbase + s * 32768;
        const uint32_t sB = sA + 16384;
#pragma unroll
        for (int j = 0; j < 4; j++) {
            int row = lrow + j * 32;
            uint32_t so = (uint32_t)(row * 128 + ((lch ^ (row & 7)) << 4));
            cp_async16(sA + so, A + (size_t)(m0 + row) * Kstride + k0 + lch * 8, 16);
            int n = n0 + row;
            int nc = (n < Nb) ? n : (Nb - 1);
            cp_async16(sB + so, B + (size_t)nc * Kstride + k0 + lch * 8,
                       (n < Nb) ? 16 : 0);
        }
    };

    float acc[4][4][4];
#pragma unroll
    for (int i = 0; i < 4; i++)
#pragma unroll
        for (int j = 0; j < 4; j++)
#pragma unroll
            for (int e = 0; e < 4; e++) acc[i][j][e] = 0.f;

    const int a_r = lane & 15;
    const int a_c = lane >> 4;
    const int b_r = ((lane >> 4) & 1) * 8 + (lane & 7);
    const int b_c = (lane >> 3) & 1;

    load_stage(0, 0);
    CP_COMMIT();

    for (int i = 0; i < nch; i++) {
        if (i + 1 < nch) load_stage((i + 1) & 1, i + 1);
        CP_COMMIT();
        CP_WAIT1();
        __syncthreads();

        const uint32_t sA = sbase + (i & 1) * 32768;
        const uint32_t sB = sA + 16384;
#pragma unroll
        for (int ks = 0; ks < 4; ks++) {
            uint32_t af[4][4], bf4[2][4];
#pragma unroll
            for (int mi = 0; mi < 4; mi++) {
                int row = wm + mi * 16 + a_r;
                int ch  = ks * 2 + a_c;
                ldsm_x4(af[mi], sA + row * 128 + ((ch ^ (row & 7)) << 4));
            }
#pragma unroll
            for (int nj = 0; nj < 2; nj++) {
                int row = wn + nj * 16 + b_r;
                int ch  = ks * 2 + b_c;
                ldsm_x4(bf4[nj], sB + row * 128 + ((ch ^ (row & 7)) << 4));
            }
#pragma unroll
            for (int mi = 0; mi < 4; mi++)
#pragma unroll
                for (int ni = 0; ni < 4; ni++)
                    mma16816(acc[mi][ni], af[mi], &bf4[ni >> 1][(ni & 1) * 2]);
        }
        __syncthreads();
    }

    // epilogue
    const int er = lane >> 2;
    const int ec = (lane & 3) * 2;
#pragma unroll
    for (int mi = 0; mi < 4; mi++) {
#pragma unroll
        for (int half = 0; half < 2; half++) {
            int m = m0 + wm + mi * 16 + er + half * 8;
            float* crow = C + (size_t)m * ldc;
#pragma unroll
            for (int ni = 0; ni < 4; ni++) {
                int n = n0 + wn + ni * 8 + ec;
                float v0 = acc[mi][ni][half * 2 + 0];
                float v1 = acc[mi][ni][half * 2 + 1];
                if (EPI == 1) {
                    v0 += bias[n];     v1 += bias[n + 1];
                    v0 = (v0 > 20.f) ? v0 : log1pf(expf(v0));
                    v1 = (v1 > 20.f) ? v1 : log1pf(expf(v1));
                }
                *(float2*)&crow[n] = make_float2(v0, v1);
            }
        }
    }
}

// ---------------- xproj split-K reduce + fused dt-rank split ----------------
__global__ void __launch_bounds__(256)
reduce_xproj(const float* __restrict__ part,
             float* __restrict__ xdbl,
             __nv_bfloat16* __restrict__ dta3)
{
    int idx = blockIdx.x * blockDim.x + threadIdx.x;
    if (idx >= MROWS * XDBL_W) return;
    int m = idx / XDBL_W;
    int n = idx - m * XDBL_W;
    float s = 0.f;
#pragma unroll
    for (int z = 0; z < NSPLITK; z++)
        s += part[(size_t)z * MROWS * XP_LD + (size_t)m * XP_LD + n];
    xdbl[idx] = s;
    if (n < DTRANK) {
        __nv_bfloat16 h, l; split2(s, h, l);
        __nv_bfloat16* o = dta3 + (size_t)m * K3DT + 3 * n;
        o[0] = h; o[1] = h; o[2] = l;
    }
}

// ---------------- conv(K=4) + SiLU + fused A-side split --------------------
__global__ void __launch_bounds__(256)
conv_silu_split(const float* __restrict__ xz,
                const float* __restrict__ conv_w,
                const float* __restrict__ conv_b,
                float* __restrict__ u,
                __nv_bfloat16* __restrict__ uh3)
{
    int idx = blockIdx.x * blockDim.x + threadIdx.x;
    if (idx >= MROWS * DMODEL) return;
    int d = idx & (DMODEL - 1);
    int m = idx >> 11;
    int l = m & (SEQ - 1);
    int b = m >> 10;

    float w0 = conv_w[d*4+0], w1 = conv_w[d*4+1],
          w2 = conv_w[d*4+2], w3 = conv_w[d*4+3];
    float acc = conv_b[d];
    size_t base = (size_t)(b * SEQ) * (2*DMODEL) + d;
    if (l >= 3) acc += w0 * xz[base + (size_t)(l-3) * (2*DMODEL)];
    if (l >= 2) acc += w1 * xz[base + (size_t)(l-2) * (2*DMODEL)];
    if (l >= 1) acc += w2 * xz[base + (size_t)(l-1) * (2*DMODEL)];
    acc += w3 * xz[base + (size_t)l * (2*DMODEL)];
    float sig = 1.f / (1.f + expf(-acc));
    float val = acc * sig;
    u[idx] = val;
    __nv_bfloat16 h, lo; split2(val, h, lo);
    __nv_bfloat16* o = uh3 + (size_t)m * K3 + 3 * d;
    o[0] = h; o[1] = h; o[2] = lo;
}

// ---------------- selective scan + gate + fused A-side split ---------------
#define DG 16
#define CL 64
__global__ void __launch_bounds__(256)
scan_kernel(const float* __restrict__ xdbl,
            const float* __restrict__ dt,
            const float* __restrict__ u,
            const float* __restrict__ xz,
            const float* __restrict__ A_log,
            const float* __restrict__ Dskip,
            __nv_bfloat16* __restrict__ yph3)
{
    const int b    = blockIdx.x >> 7;
    const int dblk = blockIdx.x & 127;
    const int d0   = dblk * DG;
    const int tid  = threadIdx.x;
    const int dloc = tid >> 4;
    const int n    = tid & 15;
    const int d    = d0 + dloc;

    const float Adn = -expf(A_log[d * DSTATE + n]);
    const float Dsk = Dskip[d];
    float h = 0.f;

    __shared__ float sdt[CL*DG], su[CL*DG], sz[CL*DG];
    __shared__ float sB[CL*DSTATE], sC[CL*DSTATE];

    for (int c = 0; c < SEQ / CL; c++) {
        const int l0 = c * CL;
        __syncthreads();
#pragma unroll
        for (int e = tid; e < CL*DG; e += 256) {
            int lr = e >> 4, el = e & 15;
            size_t row = (size_t)(b * SEQ + l0 + lr);
            sdt[e] = dt[row * DMODEL + d0 + el];
            su[e]  = u [row * DMODEL + d0 + el];
            sz[e]  = xz[row * (2*DMODEL) + DMODEL + d0 + el];
            sB[e]  = xdbl[row * XDBL_W + DTRANK + el];
            sC[e]  = xdbl[row * XDBL_W + DTRANK + DSTATE + el];
        }
        __syncthreads();

#pragma unroll 4
        for (int lr = 0; lr < CL; lr++) {
            float dtv = sdt[lr*16 + dloc];
            float uu  = su [lr*16 + dloc];
            float dA  = __expf(dtv * Adn);
            h = dA * h + (dtv * uu) * sB[lr*16 + n];
            float y = h * sC[lr*16 + n];
            y += __shfl_xor_sync(0xffffffffu, y, 8, 16);
            y += __shfl_xor_sync(0xffffffffu, y, 4, 16);
            y += __shfl_xor_sync(0xffffffffu, y, 2, 16);
            y += __shfl_xor_sync(0xffffffffu, y, 1, 16);
            if (n == 0) {
                float z   = sz[lr*16 + dloc];
                float sig = 1.f / (1.f + __expf(-z));
                float val = (y + uu * Dsk) * (z * sig);
                __nv_bfloat16 hh, ll; split2(val, hh, ll);
                __nv_bfloat16* o = yph3 +
                    (size_t)(b * SEQ + l0 + lr) * K3 + 3 * d;
                o[0] = hh; o[1] = hh; o[2] = ll;
            }
        }
    }
}

// ---------------- launch ----------------
extern "C" void kernel_launch(void* const* d_in, const int* in_sizes, int n_in,
                              void* d_out, int out_size)
{
    const float* x      = (const float*)d_in[0];
    const float* W_in   = (const float*)d_in[1];
    const float* conv_w = (const float*)d_in[2];
    const float* conv_b = (const float*)d_in[3];
    const float* W_xproj= (const float*)d_in[4];
    const float* W_dt   = (const float*)d_in[5];
    const float* b_dt   = (const float*)d_in[6];
    const float* A_log  = (const float*)d_in[7];
    const float* Dskip  = (const float*)d_in[8];
    const float* W_out  = (const float*)d_in[9];
    float* out = (float*)d_out;

    float *xz, *u, *xdbl, *dtb, *part;
    __nv_bfloat16 *xh3, *wih3, *uh3, *wxh3, *dta3, *wdt3, *yph3, *woh3;
    cudaGetSymbolAddress((void**)&xz,   g_xz);
    cudaGetSymbolAddress((void**)&u,    g_u);
    cudaGetSymbolAddress((void**)&xdbl, g_xdbl);
    cudaGetSymbolAddress((void**)&dtb,  g_dt);
    cudaGetSymbolAddress((void**)&part, g_part);
    cudaGetSymbolAddress((void**)&xh3,  g_xh3);
    cudaGetSymbolAddress((void**)&wih3, g_wih3);
    cudaGetSymbolAddress((void**)&uh3,  g_uh3);
    cudaGetSymbolAddress((void**)&wxh3, g_wxh3);
    cudaGetSymbolAddress((void**)&dta3, g_dta3);
    cudaGetSymbolAddress((void**)&wdt3, g_wdt3);
    cudaGetSymbolAddress((void**)&yph3, g_yph3);
    cudaGetSymbolAddress((void**)&woh3, g_woh3);

    cudaFuncSetAttribute(gemm_mma<0>, cudaFuncAttributeMaxDynamicSharedMemorySize, GSMEM);
    cudaFuncSetAttribute(gemm_mma<1>, cudaFuncAttributeMaxDynamicSharedMemorySize, GSMEM);

    // --- 1) split x, W_in; xz = x @ W_in^T ---
    {
        int tot = MROWS * DMODEL / 2;
        split3_kernel<1><<<(tot+255)/256, 256>>>(x, DMODEL, DMODEL, xh3, tot);
        int totw = (2*DMODEL) * DMODEL / 2;
        split3_kernel<0><<<(totw+255)/256, 256>>>(W_in, DMODEL, DMODEL, wih3, totw);
        dim3 grid((2*DMODEL)/128, MROWS/128, 1);
        gemm_mma<0><<<grid, 256, GSMEM>>>(xh3, wih3, xz, 2*DMODEL,
                                          2*DMODEL, K3, K3, 0, nullptr);
    }
    // --- 2) u = silu(conv(xz[:, :2048])), fused bf16x3 split ---
    {
        int total = MROWS * DMODEL;
        conv_silu_split<<<(total+255)/256, 256>>>(xz, conv_w, conv_b, u, uh3);
    }
    // --- 3) x_dbl = u @ W_xproj^T  (split-K x4 -> reduce with fused dt split)
    {
        int totw = XDBL_W * DMODEL / 2;
        split3_kernel<0><<<(totw+255)/256, 256>>>(W_xproj, DMODEL, DMODEL, wxh3, totw);
        dim3 grid(2, MROWS/128, NSPLITK);
        gemm_mma<0><<<grid, 256, GSMEM>>>(uh3, wxh3, part, XP_LD,
                                          XDBL_W, K3, K3/NSPLITK,
                                          (size_t)MROWS * XP_LD, nullptr);
        int tot = MROWS * XDBL_W;
        reduce_xproj<<<(tot+255)/256, 256>>>(part, xdbl, dta3);
    }
    // --- 4) dt = softplus(x_dbl[:, :128] @ W_dt^T + b_dt) ---
    {
        int totw = DMODEL * DTRANK / 2;
        split3_kernel<0><<<(totw+255)/256, 256>>>(W_dt, DTRANK, DTRANK, wdt3, totw);
        dim3 grid(DMODEL/128, MROWS/128, 1);
        gemm_mma<1><<<grid, 256, GSMEM>>>(dta3, wdt3, dtb, DMODEL,
                                          DMODEL, K3DT, K3DT, 0, b_dt);
    }
    // --- 5) selective scan + gate, fused bf16x3 split ---
    scan_kernel<<<BSZ * (DMODEL/DG), 256>>>(xdbl, dtb, u, xz, A_log, Dskip, yph3);
    // --- 6) out = ypre @ W_out^T ---
    {
        int totw = DMODEL * DMODEL / 2;
        split3_kernel<0><<<(totw+255)/256, 256>>>(W_out, DMODEL, DMODEL, woh3, totw);
        dim3 grid(DMODEL/128, MROWS/128, 1);
        gemm_mma<0><<<grid, 256, GSMEM>>>(yph3, woh3, out, DMODEL,
                                          DMODEL, K3, K3, 0, nullptr);
    }
}

// round 6
// speedup vs baseline: 1.1172x; 1.0432x over previous
#include <cuda_runtime.h>
#include <cuda_bf16.h>
#include <cstdint>

// ---------------- problem constants ----------------
#define DMODEL 2048
#define DSTATE 16
#define DTRANK 128
#define BSZ    2
#define SEQ    1024
#define MROWS  (BSZ*SEQ)            // 2048
#define XDBL_W (DTRANK + 2*DSTATE)  // 160
#define K3     (3*DMODEL)           // 6144
#define K3DT   (3*DTRANK)           // 384
#define NSPLITK 4
#define XP_LD   256

// ---------------- static scratch ----------------
__device__ float g_xz  [(size_t)MROWS * (2*DMODEL)];
__device__ float g_u   [(size_t)MROWS * DMODEL];
__device__ float g_xdbl[(size_t)MROWS * XDBL_W];
__device__ float g_dt  [(size_t)MROWS * DMODEL];
__device__ float g_part[(size_t)NSPLITK * MROWS * XP_LD];

__device__ __nv_bfloat16 g_xh3 [(size_t)MROWS  * K3];
__device__ __nv_bfloat16 g_wih3[(size_t)(2*DMODEL) * K3];
__device__ __nv_bfloat16 g_uh3 [(size_t)MROWS  * K3];
__device__ __nv_bfloat16 g_wxh3[(size_t)XDBL_W * K3];
__device__ __nv_bfloat16 g_dta3[(size_t)MROWS  * K3DT];
__device__ __nv_bfloat16 g_wdt3[(size_t)DMODEL * K3DT];
__device__ __nv_bfloat16 g_yph3[(size_t)MROWS  * K3];
__device__ __nv_bfloat16 g_woh3[(size_t)DMODEL * K3];

// ---------------- PTX helpers ----------------
__device__ __forceinline__ uint32_t smem_u32(const void* p) {
    uint32_t a;
    asm("{ .reg .u64 t; cvta.to.shared.u64 t, %1; cvt.u32.u64 %0, t; }" : "=r"(a) : "l"(p));
    return a;
}
__device__ __forceinline__ void cp_async16(uint32_t saddr, const void* gaddr, int src_bytes) {
    asm volatile("cp.async.cg.shared.global [%0], [%1], 16, %2;"
                 :: "r"(saddr), "l"(gaddr), "r"(src_bytes) : "memory");
}
#define CP_COMMIT() asm volatile("cp.async.commit_group;" ::: "memory")
#define CP_WAIT1()  asm volatile("cp.async.wait_group 1;" ::: "memory")

__device__ __forceinline__ void ldsm_x4(uint32_t* r, uint32_t addr) {
    asm volatile("ldmatrix.sync.aligned.m8n8.x4.shared.b16 {%0,%1,%2,%3}, [%4];"
                 : "=r"(r[0]), "=r"(r[1]), "=r"(r[2]), "=r"(r[3]) : "r"(addr));
}
__device__ __forceinline__ void mma16816(float* d, const uint32_t* a, const uint32_t* b) {
    asm volatile(
        "mma.sync.aligned.m16n8k16.row.col.f32.bf16.bf16.f32 "
        "{%0,%1,%2,%3}, {%4,%5,%6,%7}, {%8,%9}, {%0,%1,%2,%3};"
        : "+f"(d[0]), "+f"(d[1]), "+f"(d[2]), "+f"(d[3])
        : "r"(a[0]), "r"(a[1]), "r"(a[2]), "r"(a[3]), "r"(b[0]), "r"(b[1]));
}
__device__ __forceinline__ void split2(float v, __nv_bfloat16& h, __nv_bfloat16& l) {
    h = __float2bfloat16(v);
    l = __float2bfloat16(v - __bfloat162float(h));
}

// ---------------- B-side split core (layout [hi,lo,hi]) ----------------
__device__ __forceinline__ void split3_b_elem(const float* src, int ld, int cols,
                                              __nv_bfloat16* dst, int idx)
{
    int halfc = cols >> 1;
    int r = idx / halfc;
    int c = idx - r * halfc;
    float v0 = src[(size_t)r * ld + 2*c];
    float v1 = src[(size_t)r * ld + 2*c + 1];
    __nv_bfloat16 h0, l0, h1, l1;
    split2(v0, h0, l0); split2(v1, h1, l1);
    __nv_bfloat162* out = (__nv_bfloat162*)(dst + (size_t)r * 3 * cols + 6*c);
    __nv_bfloat162 w0, w1, w2;
    w0.x=h0; w0.y=l0; w1.x=h0; w1.y=h1; w2.x=l1; w2.y=h1;
    out[0] = w0; out[1] = w1; out[2] = w2;
}

// A-side split (layout [hi,hi,lo]) for x
__global__ void __launch_bounds__(256)
split3_a_kernel(const float* __restrict__ src, int ld, int cols,
                __nv_bfloat16* __restrict__ dst, int total)
{
    int idx = blockIdx.x * blockDim.x + threadIdx.x;
    if (idx >= total) return;
    int halfc = cols >> 1;
    int r = idx / halfc;
    int c = idx - r * halfc;
    float v0 = src[(size_t)r * ld + 2*c];
    float v1 = src[(size_t)r * ld + 2*c + 1];
    __nv_bfloat16 h0, l0, h1, l1;
    split2(v0, h0, l0); split2(v1, h1, l1);
    __nv_bfloat162* out = (__nv_bfloat162*)(dst + (size_t)r * 3 * cols + 6*c);
    __nv_bfloat162 w0, w1, w2;
    w0.x=h0; w0.y=h0; w1.x=l0; w1.y=h1; w2.x=h1; w2.y=l1;
    out[0] = w0; out[1] = w1; out[2] = w2;
}

// ---- merged weight split: W_in, W_xproj, W_dt, W_out in ONE launch ----
#define WIN_T  ((2*DMODEL)*DMODEL/2)   // 4,194,304
#define WXP_T  (XDBL_W*DMODEL/2)       //   163,840
#define WDT_T  (DMODEL*DTRANK/2)       //   131,072
#define WOUT_T (DMODEL*DMODEL/2)       // 2,097,152
#define WALL_T (WIN_T+WXP_T+WDT_T+WOUT_T)

__global__ void __launch_bounds__(256)
split_weights_kernel(const float* __restrict__ W_in,
                     const float* __restrict__ W_xproj,
                     const float* __restrict__ W_dt,
                     const float* __restrict__ W_out,
                     __nv_bfloat16* __restrict__ wih3,
                     __nv_bfloat16* __restrict__ wxh3,
                     __nv_bfloat16* __restrict__ wdt3,
                     __nv_bfloat16* __restrict__ woh3)
{
    int idx = blockIdx.x * blockDim.x + threadIdx.x;
    if (idx < WIN_T) {
        split3_b_elem(W_in, DMODEL, DMODEL, wih3, idx);
        return;
    }
    idx -= WIN_T;
    if (idx < WXP_T) {
        split3_b_elem(W_xproj, DMODEL, DMODEL, wxh3, idx);
        return;
    }
    idx -= WXP_T;
    if (idx < WDT_T) {
        split3_b_elem(W_dt, DTRANK, DTRANK, wdt3, idx);
        return;
    }
    idx -= WDT_T;
    if (idx < WOUT_T)
        split3_b_elem(W_out, DMODEL, DMODEL, woh3, idx);
}

// ---------------- bf16 tensor-core GEMM: 3-stage cp.async ------------------
// C[m,n] (+slab z) = sum_{k in segment} A[m,k]*B[n,k]
// CTA 128x128, 8 warps each 64x32, BK=64, 3-stage pipeline, 1 sync/chunk.
// EPI==1: softplus(acc + bias[n]).
#define STG   32768
#define GSMEM (3*STG)

template<int EPI>
__global__ void __launch_bounds__(256, 2)
gemm_mma(const __nv_bfloat16* __restrict__ A,
         const __nv_bfloat16* __restrict__ B,
         float* __restrict__ C, int ldc,
         int Nb, int Kstride, int Klen, size_t cslab,
         const float* __restrict__ bias)
{
    extern __shared__ __align__(1024) char smem[];
    const uint32_t sbase = smem_u32(smem);

    const int tid  = threadIdx.x;
    const int wid  = tid >> 5;
    const int lane = tid & 31;
    const int m0 = blockIdx.y << 7;
    const int n0 = blockIdx.x << 7;
    const int koff = blockIdx.z * Klen;
    C += (size_t)blockIdx.z * cslab;

    const int wm = (wid & 1) * 64;
    const int wn = (wid >> 1) * 32;
    const int nch = Klen >> 6;

    const int lrow = tid >> 3;
    const int lch  = tid & 7;
    auto load_stage = [&](uint32_t sA, int i) {
        const int k0 = koff + (i << 6);
        const uint32_t sB = sA + 16384;
#pragma unroll
        for (int j = 0; j < 4; j++) {
            int row = lrow + j * 32;
            uint32_t so = (uint32_t)(row * 128 + ((lch ^ (row & 7)) << 4));
            cp_async16(sA + so, A + (size_t)(m0 + row) * Kstride + k0 + lch * 8, 16);
            int n = n0 + row;
            int nc = (n < Nb) ? n : (Nb - 1);
            cp_async16(sB + so, B + (size_t)nc * Kstride + k0 + lch * 8,
                       (n < Nb) ? 16 : 0);
        }
    };

    float acc[4][4][4];
#pragma unroll
    for (int i = 0; i < 4; i++)
#pragma unroll
        for (int j = 0; j < 4; j++)
#pragma unroll
            for (int e = 0; e < 4; e++) acc[i][j][e] = 0.f;

    const int a_r = lane & 15;
    const int a_c = lane >> 4;
    const int b_r = ((lane >> 4) & 1) * 8 + (lane & 7);
    const int b_c = (lane >> 3) & 1;

    uint32_t buf0 = sbase, buf1 = sbase + STG, buf2 = sbase + 2*STG;

    load_stage(buf0, 0); CP_COMMIT();
    if (nch > 1) load_stage(buf1, 1);
    CP_COMMIT();

    for (int i = 0; i < nch; i++) {
        CP_WAIT1();
        __syncthreads();
        if (i + 2 < nch) load_stage(buf2, i + 2);
        CP_COMMIT();

        const uint32_t sA = buf0;
        const uint32_t sB = buf0 + 16384;
#pragma unroll
        for (int ks = 0; ks < 4; ks++) {
            uint32_t af[4][4], bf4[2][4];
#pragma unroll
            for (int mi = 0; mi < 4; mi++) {
                int row = wm + mi * 16 + a_r;
                int ch  = ks * 2 + a_c;
                ldsm_x4(af[mi], sA + row * 128 + ((ch ^ (row & 7)) << 4));
            }
#pragma unroll
            for (int nj = 0; nj < 2; nj++) {
                int row = wn + nj * 16 + b_r;
                int ch  = ks * 2 + b_c;
                ldsm_x4(bf4[nj], sB + row * 128 + ((ch ^ (row & 7)) << 4));
            }
#pragma unroll
            for (int mi = 0; mi < 4; mi++)
#pragma unroll
                for (int ni = 0; ni < 4; ni++)
                    mma16816(acc[mi][ni], af[mi], &bf4[ni >> 1][(ni & 1) * 2]);
        }
        // rotate stages
        uint32_t t = buf0; buf0 = buf1; buf1 = buf2; buf2 = t;
    }

    // epilogue
    const int er = lane >> 2;
    const int ec = (lane & 3) * 2;
#pragma unroll
    for (int mi = 0; mi < 4; mi++) {
#pragma unroll
        for (int half = 0; half < 2; half++) {
            int m = m0 + wm + mi * 16 + er + half * 8;
            float* crow = C + (size_t)m * ldc;
#pragma unroll
            for (int ni = 0; ni < 4; ni++) {
                int n = n0 + wn + ni * 8 + ec;
                float v0 = acc[mi][ni][half * 2 + 0];
                float v1 = acc[mi][ni][half * 2 + 1];
                if (EPI == 1) {
                    v0 += bias[n];     v1 += bias[n + 1];
                    v0 = (v0 > 20.f) ? v0 : log1pf(expf(v0));
                    v1 = (v1 > 20.f) ? v1 : log1pf(expf(v1));
                }
                *(float2*)&crow[n] = make_float2(v0, v1);
            }
        }
    }
}

// ---------------- xproj split-K reduce + fused dt-rank split ----------------
__global__ void __launch_bounds__(256)
reduce_xproj(const float* __restrict__ part,
             float* __restrict__ xdbl,
             __nv_bfloat16* __restrict__ dta3)
{
    int idx = blockIdx.x * blockDim.x + threadIdx.x;
    if (idx >= MROWS * XDBL_W) return;
    int m = idx / XDBL_W;
    int n = idx - m * XDBL_W;
    float s = 0.f;
#pragma unroll
    for (int z = 0; z < NSPLITK; z++)
        s += part[(size_t)z * MROWS * XP_LD + (size_t)m * XP_LD + n];
    xdbl[idx] = s;
    if (n < DTRANK) {
        __nv_bfloat16 h, l; split2(s, h, l);
        __nv_bfloat16* o = dta3 + (size_t)m * K3DT + 3 * n;
        o[0] = h; o[1] = h; o[2] = l;
    }
}

// ---------------- conv(K=4) + SiLU + fused A-side split (4 l per thread) ---
__global__ void __launch_bounds__(256)
conv_silu_split(const float* __restrict__ xz,
                const float* __restrict__ conv_w,
                const float* __restrict__ conv_b,
                float* __restrict__ u,
                __nv_bfloat16* __restrict__ uh3)
{
    int idx = blockIdx.x * blockDim.x + threadIdx.x;
    if (idx >= MROWS * DMODEL / 4) return;
    int d = idx & (DMODEL - 1);
    int t = idx >> 11;            // 0..511 = b*256 + l4
    int l0 = (t & 255) << 2;
    int b  = t >> 8;

    float w0 = conv_w[d*4+0], w1 = conv_w[d*4+1],
          w2 = conv_w[d*4+2], w3 = conv_w[d*4+3];
    float cb = conv_b[d];

    size_t base = (size_t)(b * SEQ) * (2*DMODEL) + d;
    float v[7];
#pragma unroll
    for (int j = 0; j < 7; j++) {
        int l = l0 - 3 + j;
        v[j] = (l >= 0) ? xz[base + (size_t)l * (2*DMODEL)] : 0.f;
    }
#pragma unroll
    for (int k = 0; k < 4; k++) {
        float acc = cb + w0*v[k] + w1*v[k+1] + w2*v[k+2] + w3*v[k+3];
        float sig = 1.f / (1.f + __expf(-acc));
        float val = acc * sig;
        int m = b * SEQ + l0 + k;
        u[(size_t)m * DMODEL + d] = val;
        __nv_bfloat16 h, lo; split2(val, h, lo);
        __nv_bfloat16* o = uh3 + (size_t)m * K3 + 3 * d;
        o[0] = h; o[1] = h; o[2] = lo;
    }
}

// ---------------- selective scan + gate + fused A-side split ---------------
#define DG 16
#define CL 64
__global__ void __launch_bounds__(256)
scan_kernel(const float* __restrict__ xdbl,
            const float* __restrict__ dt,
            const float* __restrict__ u,
            const float* __restrict__ xz,
            const float* __restrict__ A_log,
            const float* __restrict__ Dskip,
            __nv_bfloat16* __restrict__ yph3)
{
    const int b    = blockIdx.x >> 7;
    const int dblk = blockIdx.x & 127;
    const int d0   = dblk * DG;
    const int tid  = threadIdx.x;
    const int dloc = tid >> 4;
    const int n    = tid & 15;
    const int d    = d0 + dloc;

    const float Adn = -expf(A_log[d * DSTATE + n]);
    const float Dsk = Dskip[d];
    float h = 0.f;

    __shared__ float sdt[CL*DG], su[CL*DG], sz[CL*DG];
    __shared__ float sB[CL*DSTATE], sC[CL*DSTATE];

    for (int c = 0; c < SEQ / CL; c++) {
        const int l0 = c * CL;
        __syncthreads();
#pragma unroll
        for (int e = tid; e < CL*DG; e += 256) {
            int lr = e >> 4, el = e & 15;
            size_t row = (size_t)(b * SEQ + l0 + lr);
            sdt[e] = dt[row * DMODEL + d0 + el];
            su[e]  = u [row * DMODEL + d0 + el];
            sz[e]  = xz[row * (2*DMODEL) + DMODEL + d0 + el];
            sB[e]  = xdbl[row * XDBL_W + DTRANK + el];
            sC[e]  = xdbl[row * XDBL_W + DTRANK + DSTATE + el];
        }
        __syncthreads();

#pragma unroll 4
        for (int lr = 0; lr < CL; lr++) {
            float dtv = sdt[lr*16 + dloc];
            float uu  = su [lr*16 + dloc];
            float dA  = __expf(dtv * Adn);
            h = dA * h + (dtv * uu) * sB[lr*16 + n];
            float y = h * sC[lr*16 + n];
            y += __shfl_xor_sync(0xffffffffu, y, 8, 16);
            y += __shfl_xor_sync(0xffffffffu, y, 4, 16);
            y += __shfl_xor_sync(0xffffffffu, y, 2, 16);
            y += __shfl_xor_sync(0xffffffffu, y, 1, 16);
            if (n == 0) {
                float z   = sz[lr*16 + dloc];
                float sig = 1.f / (1.f + __expf(-z));
                float val = (y + uu * Dsk) * (z * sig);
                __nv_bfloat16 hh, ll; split2(val, hh, ll);
                __nv_bfloat16* o = yph3 +
                    (size_t)(b * SEQ + l0 + lr) * K3 + 3 * d;
                o[0] = hh; o[1] = hh; o[2] = ll;
            }
        }
    }
}

// ---------------- launch ----------------
extern "C" void kernel_launch(void* const* d_in, const int* in_sizes, int n_in,
                              void* d_out, int out_size)
{
    const float* x      = (const float*)d_in[0];
    const float* W_in   = (const float*)d_in[1];
    const float* conv_w = (const float*)d_in[2];
    const float* conv_b = (const float*)d_in[3];
    const float* W_xproj= (const float*)d_in[4];
    const float* W_dt   = (const float*)d_in[5];
    const float* b_dt   = (const float*)d_in[6];
    const float* A_log  = (const float*)d_in[7];
    const float* Dskip  = (const float*)d_in[8];
    const float* W_out  = (const float*)d_in[9];
    float* out = (float*)d_out;

    float *xz, *u, *xdbl, *dtb, *part;
    __nv_bfloat16 *xh3, *wih3, *uh3, *wxh3, *dta3, *wdt3, *yph3, *woh3;
    cudaGetSymbolAddress((void**)&xz,   g_xz);
    cudaGetSymbolAddress((void**)&u,    g_u);
    cudaGetSymbolAddress((void**)&xdbl, g_xdbl);
    cudaGetSymbolAddress((void**)&dtb,  g_dt);
    cudaGetSymbolAddress((void**)&part, g_part);
    cudaGetSymbolAddress((void**)&xh3,  g_xh3);
    cudaGetSymbolAddress((void**)&wih3, g_wih3);
    cudaGetSymbolAddress((void**)&uh3,  g_uh3);
    cudaGetSymbolAddress((void**)&wxh3, g_wxh3);
    cudaGetSymbolAddress((void**)&dta3, g_dta3);
    cudaGetSymbolAddress((void**)&wdt3, g_wdt3);
    cudaGetSymbolAddress((void**)&yph3, g_yph3);
    cudaGetSymbolAddress((void**)&woh3, g_woh3);

    cudaFuncSetAttribute(gemm_mma<0>, cudaFuncAttributeMaxDynamicSharedMemorySize, GSMEM);
    cudaFuncSetAttribute(gemm_mma<1>, cudaFuncAttributeMaxDynamicSharedMemorySize, GSMEM);

    // --- 0) split all weights (one launch) + x ---
    split_weights_kernel<<<(WALL_T + 255)/256, 256>>>(
        W_in, W_xproj, W_dt, W_out, wih3, wxh3, wdt3, woh3);
    {
        int tot = MROWS * DMODEL / 2;
        split3_a_kernel<<<(tot+255)/256, 256>>>(x, DMODEL, DMODEL, xh3, tot);
    }
    // --- 1) xz = x @ W_in^T ---
    {
        dim3 grid((2*DMODEL)/128, MROWS/128, 1);
        gemm_mma<0><<<grid, 256, GSMEM>>>(xh3, wih3, xz, 2*DMODEL,
                                          2*DMODEL, K3, K3, 0, nullptr);
    }
    // --- 2) u = silu(conv(xz[:, :2048])), fused bf16x3 split ---
    {
        int total = MROWS * DMODEL / 4;
        conv_silu_split<<<(total + 255)/256, 256>>>(xz, conv_w, conv_b, u, uh3);
    }
    // --- 3) x_dbl = u @ W_xproj^T  (split-K x4 -> reduce with fused dt split)
    {
        dim3 grid(2, MROWS/128, NSPLITK);
        gemm_mma<0><<<grid, 256, GSMEM>>>(uh3, wxh3, part, XP_LD,
                                          XDBL_W, K3, K3/NSPLITK,
                                          (size_t)MROWS * XP_LD, nullptr);
        int tot = MROWS * XDBL_W;
        reduce_xproj<<<(tot+255)/256, 256>>>(part, xdbl, dta3);
    }
    // --- 4) dt = softplus(x_dbl[:, :128] @ W_dt^T + b_dt) ---
    {
        dim3 grid(DMODEL/128, MROWS/128, 1);
        gemm_mma<1><<<grid, 256, GSMEM>>>(dta3, wdt3, dtb, DMODEL,
                                          DMODEL, K3DT, K3DT, 0, b_dt);
    }
    // --- 5) selective scan + gate, fused bf16x3 split ---
    scan_kernel<<<BSZ * (DMODEL/DG), 256>>>(xdbl, dtb, u, xz, A_log, Dskip, yph3);
    // --- 6) out = ypre @ W_out^T ---
    {
        dim3 grid(DMODEL/128, MROWS/128, 1);
        gemm_mma<0><<<grid, 256, GSMEM>>>(yph3, woh3, out, DMODEL,
                                          DMODEL, K3, K3, 0, nullptr);
    }
}

// round 7
// speedup vs baseline: 1.1244x; 1.0064x over previous
#include <cuda_runtime.h>
#include <cuda_bf16.h>
#include <cstdint>

// ---------------- problem constants ----------------
#define DMODEL 2048
#define DSTATE 16
#define DTRANK 128
#define BSZ    2
#define SEQ    1024
#define MROWS  (BSZ*SEQ)            // 2048
#define XDBL_W (DTRANK + 2*DSTATE)  // 160
#define K3     (3*DMODEL)           // 6144
#define K3DT   (3*DTRANK)           // 384
#define NSPLITK 8
#define XP_LD   256

// ---------------- static scratch ----------------
__device__ float g_xz  [(size_t)MROWS * (2*DMODEL)];
__device__ float g_u   [(size_t)MROWS * DMODEL];
__device__ float g_xdbl[(size_t)MROWS * XDBL_W];
__device__ float g_dt  [(size_t)MROWS * DMODEL];
__device__ float g_part[(size_t)NSPLITK * MROWS * XP_LD];

__device__ __nv_bfloat16 g_xh3 [(size_t)MROWS  * K3];
__device__ __nv_bfloat16 g_wih3[(size_t)(2*DMODEL) * K3];
__device__ __nv_bfloat16 g_uh3 [(size_t)MROWS  * K3];
__device__ __nv_bfloat16 g_wxh3[(size_t)XDBL_W * K3];
__device__ __nv_bfloat16 g_dta3[(size_t)MROWS  * K3DT];
__device__ __nv_bfloat16 g_wdt3[(size_t)DMODEL * K3DT];
__device__ __nv_bfloat16 g_yph3[(size_t)MROWS  * K3];
__device__ __nv_bfloat16 g_woh3[(size_t)DMODEL * K3];

// ---------------- PTX helpers ----------------
__device__ __forceinline__ uint32_t smem_u32(const void* p) {
    uint32_t a;
    asm("{ .reg .u64 t; cvta.to.shared.u64 t, %1; cvt.u32.u64 %0, t; }" : "=r"(a) : "l"(p));
    return a;
}
__device__ __forceinline__ void cp_async16(uint32_t saddr, const void* gaddr, int src_bytes) {
    asm volatile("cp.async.cg.shared.global [%0], [%1], 16, %2;"
                 :: "r"(saddr), "l"(gaddr), "r"(src_bytes) : "memory");
}
#define CP_COMMIT() asm volatile("cp.async.commit_group;" ::: "memory")
#define CP_WAIT1()  asm volatile("cp.async.wait_group 1;" ::: "memory")

__device__ __forceinline__ void ldsm_x4(uint32_t* r, uint32_t addr) {
    asm volatile("ldmatrix.sync.aligned.m8n8.x4.shared.b16 {%0,%1,%2,%3}, [%4];"
                 : "=r"(r[0]), "=r"(r[1]), "=r"(r[2]), "=r"(r[3]) : "r"(addr));
}
__device__ __forceinline__ void mma16816(float* d, const uint32_t* a, const uint32_t* b) {
    asm volatile(
        "mma.sync.aligned.m16n8k16.row.col.f32.bf16.bf16.f32 "
        "{%0,%1,%2,%3}, {%4,%5,%6,%7}, {%8,%9}, {%0,%1,%2,%3};"
        : "+f"(d[0]), "+f"(d[1]), "+f"(d[2]), "+f"(d[3])
        : "r"(a[0]), "r"(a[1]), "r"(a[2]), "r"(a[3]), "r"(b[0]), "r"(b[1]));
}
__device__ __forceinline__ void split2(float v, __nv_bfloat16& h, __nv_bfloat16& l) {
    h = __float2bfloat16(v);
    l = __float2bfloat16(v - __bfloat162float(h));
}
__device__ __forceinline__ uint32_t pk(__nv_bfloat16 a, __nv_bfloat16 b) {
    __nv_bfloat162 t; t.x = a; t.y = b;
    uint32_t r; *(__nv_bfloat162*)&r = t; return r;
}

// ---------------- vectorized split quads (4 pairs = 8 floats / thread) -----
// A-side layout per k: [hi,hi,lo]; B-side: [hi,lo,hi].
template<int ASIDE>
__device__ __forceinline__ void split3_quad(const float* __restrict__ src,
                                            int ld, int cols,
                                            __nv_bfloat16* __restrict__ dst, int q)
{
    int qpr = cols >> 3;               // 8-float groups per row
    int r = q / qpr;
    int c8 = (q - r * qpr) << 3;       // starting column
    const float4* s = (const float4*)(src + (size_t)r * ld + c8);
    float4 v0 = s[0], v1 = s[1];
    float vv[8] = {v0.x, v0.y, v0.z, v0.w, v1.x, v1.y, v1.z, v1.w};
    __nv_bfloat16 H[8], L[8];
#pragma unroll
    for (int j = 0; j < 8; j++) split2(vv[j], H[j], L[j]);

    uint32_t w[12];
#pragma unroll
    for (int p = 0; p < 4; p++) {       // per pair (2k): 3 words
        int e = 2*p, o = 2*p + 1;
        if (ASIDE) {                    // [He,He,Le, Ho,Ho,Lo]
            w[3*p+0] = pk(H[e], H[e]);
            w[3*p+1] = pk(L[e], H[o]);
            w[3*p+2] = pk(H[o], L[o]);
        } else {                        // [He,Le,He, Ho,Lo,Ho]
            w[3*p+0] = pk(H[e], L[e]);
            w[3*p+1] = pk(H[e], H[o]);
            w[3*p+2] = pk(L[o], H[o]);
        }
    }
    uint4* out = (uint4*)(dst + (size_t)r * 3 * cols + 3 * c8);
    out[0] = make_uint4(w[0], w[1], w[2],  w[3]);
    out[1] = make_uint4(w[4], w[5], w[6],  w[7]);
    out[2] = make_uint4(w[8], w[9], w[10], w[11]);
}

// ---- ONE mega split launch: W_in, W_xproj, W_dt, W_out (B-side) + x (A) ---
#define WIN_Q  ((2*DMODEL)*DMODEL/8)   // 1,048,576
#define WXP_Q  (XDBL_W*DMODEL/8)       //    40,960
#define WDT_Q  (DMODEL*DTRANK/8)       //    32,768
#define WOUT_Q (DMODEL*DMODEL/8)       //   524,288
#define X_Q    (MROWS*DMODEL/8)        //   524,288
#define ALL_Q  (WIN_Q+WXP_Q+WDT_Q+WOUT_Q+X_Q)

__global__ void __launch_bounds__(256)
mega_split_kernel(const float* __restrict__ W_in,
                  const float* __restrict__ W_xproj,
                  const float* __restrict__ W_dt,
                  const float* __restrict__ W_out,
                  const float* __restrict__ x,
                  __nv_bfloat16* __restrict__ wih3,
                  __nv_bfloat16* __restrict__ wxh3,
                  __nv_bfloat16* __restrict__ wdt3,
                  __nv_bfloat16* __restrict__ woh3,
                  __nv_bfloat16* __restrict__ xh3)
{
    int q = blockIdx.x * blockDim.x + threadIdx.x;
    if (q < WIN_Q)  { split3_quad<0>(W_in,   DMODEL, DMODEL, wih3, q); return; }
    q -= WIN_Q;
    if (q < WXP_Q)  { split3_quad<0>(W_xproj, DMODEL, DMODEL, wxh3, q); return; }
    q -= WXP_Q;
    if (q < WDT_Q)  { split3_quad<0>(W_dt,   DTRANK, DTRANK, wdt3, q); return; }
    q -= WDT_Q;
    if (q < WOUT_Q) { split3_quad<0>(W_out,  DMODEL, DMODEL, woh3, q); return; }
    q -= WOUT_Q;
    if (q < X_Q)      split3_quad<1>(x,      DMODEL, DMODEL, xh3,  q);
}

// ---------------- bf16 tensor-core GEMM: 3-stage cp.async ------------------
#define STG   32768
#define GSMEM (3*STG)

template<int EPI>
__global__ void __launch_bounds__(256, 2)
gemm_mma(const __nv_bfloat16* __restrict__ A,
         const __nv_bfloat16* __restrict__ B,
         float* __restrict__ C, int ldc,
         int Nb, int Kstride, int Klen, size_t cslab,
         const float* __restrict__ bias)
{
    extern __shared__ __align__(1024) char smem[];
    const uint32_t sbase = smem_u32(smem);

    const int tid  = threadIdx.x;
    const int wid  = tid >> 5;
    const int lane = tid & 31;
    const int m0 = blockIdx.y << 7;
    const int n0 = blockIdx.x << 7;
    const int koff = blockIdx.z * Klen;
    C += (size_t)blockIdx.z * cslab;

    const int wm = (wid & 1) * 64;
    const int wn = (wid >> 1) * 32;
    const int nch = Klen >> 6;

    const int lrow = tid >> 3;
    const int lch  = tid & 7;
    auto load_stage = [&](uint32_t sA, int i) {
        const int k0 = koff + (i << 6);
        const uint32_t sB = sA + 16384;
#pragma unroll
        for (int j = 0; j < 4; j++) {
            int row = lrow + j * 32;
            uint32_t so = (uint32_t)(row * 128 + ((lch ^ (row & 7)) << 4));
            cp_async16(sA + so, A + (size_t)(m0 + row) * Kstride + k0 + lch * 8, 16);
            int n = n0 + row;
            int nc = (n < Nb) ? n : (Nb - 1);
            cp_async16(sB + so, B + (size_t)nc * Kstride + k0 + lch * 8,
                       (n < Nb) ? 16 : 0);
        }
    };

    float acc[4][4][4];
#pragma unroll
    for (int i = 0; i < 4; i++)
#pragma unroll
        for (int j = 0; j < 4; j++)
#pragma unroll
            for (int e = 0; e < 4; e++) acc[i][j][e] = 0.f;

    const int a_r = lane & 15;
    const int a_c = lane >> 4;
    const int b_r = ((lane >> 4) & 1) * 8 + (lane & 7);
    const int b_c = (lane >> 3) & 1;

    uint32_t buf0 = sbase, buf1 = sbase + STG, buf2 = sbase + 2*STG;

    load_stage(buf0, 0); CP_COMMIT();
    if (nch > 1) load_stage(buf1, 1);
    CP_COMMIT();

    for (int i = 0; i < nch; i++) {
        CP_WAIT1();
        __syncthreads();
        if (i + 2 < nch) load_stage(buf2, i + 2);
        CP_COMMIT();

        const uint32_t sA = buf0;
        const uint32_t sB = buf0 + 16384;
#pragma unroll
        for (int ks = 0; ks < 4; ks++) {
            uint32_t af[4][4], bf4[2][4];
#pragma unroll
            for (int mi = 0; mi < 4; mi++) {
                int row = wm + mi * 16 + a_r;
                int ch  = ks * 2 + a_c;
                ldsm_x4(af[mi], sA + row * 128 + ((ch ^ (row & 7)) << 4));
            }
#pragma unroll
            for (int nj = 0; nj < 2; nj++) {
                int row = wn + nj * 16 + b_r;
                int ch  = ks * 2 + b_c;
                ldsm_x4(bf4[nj], sB + row * 128 + ((ch ^ (row & 7)) << 4));
            }
#pragma unroll
            for (int mi = 0; mi < 4; mi++)
#pragma unroll
                for (int ni = 0; ni < 4; ni++)
                    mma16816(acc[mi][ni], af[mi], &bf4[ni >> 1][(ni & 1) * 2]);
        }
        uint32_t t = buf0; buf0 = buf1; buf1 = buf2; buf2 = t;
    }

    const int er = lane >> 2;
    const int ec = (lane & 3) * 2;
#pragma unroll
    for (int mi = 0; mi < 4; mi++) {
#pragma unroll
        for (int half = 0; half < 2; half++) {
            int m = m0 + wm + mi * 16 + er + half * 8;
            float* crow = C + (size_t)m * ldc;
#pragma unroll
            for (int ni = 0; ni < 4; ni++) {
                int n = n0 + wn + ni * 8 + ec;
                float v0 = acc[mi][ni][half * 2 + 0];
                float v1 = acc[mi][ni][half * 2 + 1];
                if (EPI == 1) {
                    v0 += bias[n];     v1 += bias[n + 1];
                    v0 = (v0 > 20.f) ? v0 : log1pf(expf(v0));
                    v1 = (v1 > 20.f) ? v1 : log1pf(expf(v1));
                }
                *(float2*)&crow[n] = make_float2(v0, v1);
            }
        }
    }
}

// ---------------- xproj split-K reduce + fused dt-rank split ----------------
__global__ void __launch_bounds__(256)
reduce_xproj(const float* __restrict__ part,
             float* __restrict__ xdbl,
             __nv_bfloat16* __restrict__ dta3)
{
    int idx = blockIdx.x * blockDim.x + threadIdx.x;
    if (idx >= MROWS * XDBL_W) return;
    int m = idx / XDBL_W;
    int n = idx - m * XDBL_W;
    float s = 0.f;
#pragma unroll
    for (int z = 0; z < NSPLITK; z++)
        s += part[(size_t)z * MROWS * XP_LD + (size_t)m * XP_LD + n];
    xdbl[idx] = s;
    if (n < DTRANK) {
        __nv_bfloat16 h, l; split2(s, h, l);
        __nv_bfloat16* o = dta3 + (size_t)m * K3DT + 3 * n;
        o[0] = h; o[1] = h; o[2] = l;
    }
}

// ---------------- conv(K=4) + SiLU + fused A-side split (4 l per thread) ---
__global__ void __launch_bounds__(256)
conv_silu_split(const float* __restrict__ xz,
                const float* __restrict__ conv_w,
                const float* __restrict__ conv_b,
                float* __restrict__ u,
                __nv_bfloat16* __restrict__ uh3)
{
    int idx = blockIdx.x * blockDim.x + threadIdx.x;
    if (idx >= MROWS * DMODEL / 4) return;
    int d = idx & (DMODEL - 1);
    int t = idx >> 11;
    int l0 = (t & 255) << 2;
    int b  = t >> 8;

    float w0 = conv_w[d*4+0], w1 = conv_w[d*4+1],
          w2 = conv_w[d*4+2], w3 = conv_w[d*4+3];
    float cb = conv_b[d];

    size_t base = (size_t)(b * SEQ) * (2*DMODEL) + d;
    float v[7];
#pragma unroll
    for (int j = 0; j < 7; j++) {
        int l = l0 - 3 + j;
        v[j] = (l >= 0) ? xz[base + (size_t)l * (2*DMODEL)] : 0.f;
    }
#pragma unroll
    for (int k = 0; k < 4; k++) {
        float acc = cb + w0*v[k] + w1*v[k+1] + w2*v[k+2] + w3*v[k+3];
        float sig = 1.f / (1.f + __expf(-acc));
        float val = acc * sig;
        int m = b * SEQ + l0 + k;
        u[(size_t)m * DMODEL + d] = val;
        __nv_bfloat16 h, lo; split2(val, h, lo);
        __nv_bfloat16* o = uh3 + (size_t)m * K3 + 3 * d;
        o[0] = h; o[1] = h; o[2] = lo;
    }
}

// ---------------- selective scan + gate + fused A-side split ---------------
#define DG 16
#define CL 64
__global__ void __launch_bounds__(256)
scan_kernel(const float* __restrict__ xdbl,
            const float* __restrict__ dt,
            const float* __restrict__ u,
            const float* __restrict__ xz,
            const float* __restrict__ A_log,
            const float* __restrict__ Dskip,
            __nv_bfloat16* __restrict__ yph3)
{
    const int b    = blockIdx.x >> 7;
    const int dblk = blockIdx.x & 127;
    const int d0   = dblk * DG;
    const int tid  = threadIdx.x;
    const int dloc = tid >> 4;
    const int n    = tid & 15;
    const int d    = d0 + dloc;

    const float Adn = -expf(A_log[d * DSTATE + n]);
    const float Dsk = Dskip[d];
    float h = 0.f;

    __shared__ float sdt[CL*DG], su[CL*DG], sz[CL*DG];
    __shared__ float sB[CL*DSTATE], sC[CL*DSTATE];

    for (int c = 0; c < SEQ / CL; c++) {
        const int l0 = c * CL;
        __syncthreads();
#pragma unroll
        for (int e = tid; e < CL*DG; e += 256) {
            int lr = e >> 4, el = e & 15;
            size_t row = (size_t)(b * SEQ + l0 + lr);
            sdt[e] = dt[row * DMODEL + d0 + el];
            su[e]  = u [row * DMODEL + d0 + el];
            sz[e]  = xz[row * (2*DMODEL) + DMODEL + d0 + el];
            sB[e]  = xdbl[row * XDBL_W + DTRANK + el];
            sC[e]  = xdbl[row * XDBL_W + DTRANK + DSTATE + el];
        }
        __syncthreads();

#pragma unroll 8
        for (int lr = 0; lr < CL; lr++) {
            float dtv = sdt[lr*16 + dloc];
            float uu  = su [lr*16 + dloc];
            float dA  = __expf(dtv * Adn);
            h = dA * h + (dtv * uu) * sB[lr*16 + n];
            float y = h * sC[lr*16 + n];
            y += __shfl_xor_sync(0xffffffffu, y, 8, 16);
            y += __shfl_xor_sync(0xffffffffu, y, 4, 16);
            y += __shfl_xor_sync(0xffffffffu, y, 2, 16);
            y += __shfl_xor_sync(0xffffffffu, y, 1, 16);
            if (n == 0) {
                float z   = sz[lr*16 + dloc];
                float sig = 1.f / (1.f + __expf(-z));
                float val = (y + uu * Dsk) * (z * sig);
                __nv_bfloat16 hh, ll; split2(val, hh, ll);
                __nv_bfloat16* o = yph3 +
                    (size_t)(b * SEQ + l0 + lr) * K3 + 3 * d;
                o[0] = hh; o[1] = hh; o[2] = ll;
            }
        }
    }
}

// ---------------- launch ----------------
extern "C" void kernel_launch(void* const* d_in, const int* in_sizes, int n_in,
                              void* d_out, int out_size)
{
    const float* x      = (const float*)d_in[0];
    const float* W_in   = (const float*)d_in[1];
    const float* conv_w = (const float*)d_in[2];
    const float* conv_b = (const float*)d_in[3];
    const float* W_xproj= (const float*)d_in[4];
    const float* W_dt   = (const float*)d_in[5];
    const float* b_dt   = (const float*)d_in[6];
    const float* A_log  = (const float*)d_in[7];
    const float* Dskip  = (const float*)d_in[8];
    const float* W_out  = (const float*)d_in[9];
    float* out = (float*)d_out;

    float *xz, *u, *xdbl, *dtb, *part;
    __nv_bfloat16 *xh3, *wih3, *uh3, *wxh3, *dta3, *wdt3, *yph3, *woh3;
    cudaGetSymbolAddress((void**)&xz,   g_xz);
    cudaGetSymbolAddress((void**)&u,    g_u);
    cudaGetSymbolAddress((void**)&xdbl, g_xdbl);
    cudaGetSymbolAddress((void**)&dtb,  g_dt);
    cudaGetSymbolAddress((void**)&part, g_part);
    cudaGetSymbolAddress((void**)&xh3,  g_xh3);
    cudaGetSymbolAddress((void**)&wih3, g_wih3);
    cudaGetSymbolAddress((void**)&uh3,  g_uh3);
    cudaGetSymbolAddress((void**)&wxh3, g_wxh3);
    cudaGetSymbolAddress((void**)&dta3, g_dta3);
    cudaGetSymbolAddress((void**)&wdt3, g_wdt3);
    cudaGetSymbolAddress((void**)&yph3, g_yph3);
    cudaGetSymbolAddress((void**)&woh3, g_woh3);

    cudaFuncSetAttribute(gemm_mma<0>, cudaFuncAttributeMaxDynamicSharedMemorySize, GSMEM);
    cudaFuncSetAttribute(gemm_mma<1>, cudaFuncAttributeMaxDynamicSharedMemorySize, GSMEM);

    // --- 0) one mega split launch: all weights + x ---
    mega_split_kernel<<<(ALL_Q + 255)/256, 256>>>(
        W_in, W_xproj, W_dt, W_out, x, wih3, wxh3, wdt3, woh3, xh3);

    // --- 1) xz = x @ W_in^T ---
    {
        dim3 grid((2*DMODEL)/128, MROWS/128, 1);
        gemm_mma<0><<<grid, 256, GSMEM>>>(xh3, wih3, xz, 2*DMODEL,
                                          2*DMODEL, K3, K3, 0, nullptr);
    }
    // --- 2) u = silu(conv(xz[:, :2048])), fused bf16x3 split ---
    {
        int total = MROWS * DMODEL / 4;
        conv_silu_split<<<(total + 255)/256, 256>>>(xz, conv_w, conv_b, u, uh3);
    }
    // --- 3) x_dbl = u @ W_xproj^T  (split-K x8 -> reduce with fused dt split)
    {
        dim3 grid(2, MROWS/128, NSPLITK);
        gemm_mma<0><<<grid, 256, GSMEM>>>(uh3, wxh3, part, XP_LD,
                                          XDBL_W, K3, K3/NSPLITK,
                                          (size_t)MROWS * XP_LD, nullptr);
        int tot = MROWS * XDBL_W;
        reduce_xproj<<<(tot+255)/256, 256>>>(part, xdbl, dta3);
    }
    // --- 4) dt = softplus(x_dbl[:, :128] @ W_dt^T + b_dt) ---
    {
        dim3 grid(DMODEL/128, MROWS/128, 1);
        gemm_mma<1><<<grid, 256, GSMEM>>>(dta3, wdt3, dtb, DMODEL,
                                          DMODEL, K3DT, K3DT, 0, b_dt);
    }
    // --- 5) selective scan + gate, fused bf16x3 split ---
    scan_kernel<<<BSZ * (DMODEL/DG), 256>>>(xdbl, dtb, u, xz, A_log, Dskip, yph3);
    // --- 6) out = ypre @ W_out^T ---
    {
        dim3 grid(DMODEL/128, MROWS/128, 1);
        gemm_mma<0><<<grid, 256, GSMEM>>>(yph3, woh3, out, DMODEL,
                                          DMODEL, K3, K3, 0, nullptr);
    }
}

// round 8
// speedup vs baseline: 1.2131x; 1.0789x over previous
#include <cuda_runtime.h>
#include <cuda_bf16.h>
#include <cuda_fp16.h>
#include <cstdint>

// ---------------- problem constants ----------------
#define DMODEL 2048
#define DSTATE 16
#define DTRANK 128
#define BSZ    2
#define SEQ    1024
#define MROWS  (BSZ*SEQ)            // 2048
#define XDBL_W (DTRANK + 2*DSTATE)  // 160
#define K3     (3*DMODEL)           // 6144
#define K3DT   (3*DTRANK)           // 384
#define K2OUT  (2*DMODEL)           // 4096 (fp16 2-term expanded K)
#define NSPLITK 8
#define XP_LD   256

// ---------------- static scratch ----------------
__device__ float g_xz  [(size_t)MROWS * (2*DMODEL)];
__device__ float g_u   [(size_t)MROWS * DMODEL];
__device__ float g_xdbl[(size_t)MROWS * XDBL_W];
__device__ float g_dt  [(size_t)MROWS * DMODEL];
__device__ float g_part[(size_t)NSPLITK * MROWS * XP_LD];

__device__ __nv_bfloat16 g_xh3 [(size_t)MROWS  * K3];
__device__ __nv_bfloat16 g_wih3[(size_t)(2*DMODEL) * K3];
__device__ __nv_bfloat16 g_uh3 [(size_t)MROWS  * K3];
__device__ __nv_bfloat16 g_wxh3[(size_t)XDBL_W * K3];
__device__ __nv_bfloat16 g_dta3[(size_t)MROWS  * K3DT];
__device__ __nv_bfloat16 g_wdt3[(size_t)DMODEL * K3DT];
__device__ __half        g_yph2[(size_t)MROWS  * K2OUT];  // fp16 2-term A
__device__ __half        g_woh2[(size_t)DMODEL * K2OUT];  // fp16 hi-dup B

// ---------------- PTX helpers ----------------
__device__ __forceinline__ uint32_t smem_u32(const void* p) {
    uint32_t a;
    asm("{ .reg .u64 t; cvta.to.shared.u64 t, %1; cvt.u32.u64 %0, t; }" : "=r"(a) : "l"(p));
    return a;
}
__device__ __forceinline__ void cp_async16(uint32_t saddr, const void* gaddr, int src_bytes) {
    asm volatile("cp.async.cg.shared.global [%0], [%1], 16, %2;"
                 :: "r"(saddr), "l"(gaddr), "r"(src_bytes) : "memory");
}
#define CP_COMMIT() asm volatile("cp.async.commit_group;" ::: "memory")
#define CP_WAIT1()  asm volatile("cp.async.wait_group 1;" ::: "memory")

__device__ __forceinline__ void ldsm_x4(uint32_t* r, uint32_t addr) {
    asm volatile("ldmatrix.sync.aligned.m8n8.x4.shared.b16 {%0,%1,%2,%3}, [%4];"
                 : "=r"(r[0]), "=r"(r[1]), "=r"(r[2]), "=r"(r[3]) : "r"(addr));
}
template<int F16>
__device__ __forceinline__ void mma16816(float* d, const uint32_t* a, const uint32_t* b) {
    if (F16)
        asm volatile(
            "mma.sync.aligned.m16n8k16.row.col.f32.f16.f16.f32 "
            "{%0,%1,%2,%3}, {%4,%5,%6,%7}, {%8,%9}, {%0,%1,%2,%3};"
            : "+f"(d[0]), "+f"(d[1]), "+f"(d[2]), "+f"(d[3])
            : "r"(a[0]), "r"(a[1]), "r"(a[2]), "r"(a[3]), "r"(b[0]), "r"(b[1]));
    else
        asm volatile(
            "mma.sync.aligned.m16n8k16.row.col.f32.bf16.bf16.f32 "
            "{%0,%1,%2,%3}, {%4,%5,%6,%7}, {%8,%9}, {%0,%1,%2,%3};"
            : "+f"(d[0]), "+f"(d[1]), "+f"(d[2]), "+f"(d[3])
            : "r"(a[0]), "r"(a[1]), "r"(a[2]), "r"(a[3]), "r"(b[0]), "r"(b[1]));
}
__device__ __forceinline__ void split2(float v, __nv_bfloat16& h, __nv_bfloat16& l) {
    h = __float2bfloat16(v);
    l = __float2bfloat16(v - __bfloat162float(h));
}
__device__ __forceinline__ uint32_t pk(__nv_bfloat16 a, __nv_bfloat16 b) {
    __nv_bfloat162 t; t.x = a; t.y = b;
    uint32_t r; *(__nv_bfloat162*)&r = t; return r;
}
__device__ __forceinline__ uint32_t pkh(__half a, __half b) {
    __half2 t; t.x = a; t.y = b;
    uint32_t r; *(__half2*)&r = t; return r;
}

// ---------------- vectorized bf16x3 split quads ----------------
template<int ASIDE>
__device__ __forceinline__ void split3_quad(const float* __restrict__ src,
                                            int ld, int cols,
                                            __nv_bfloat16* __restrict__ dst, int q)
{
    int qpr = cols >> 3;
    int r = q / qpr;
    int c8 = (q - r * qpr) << 3;
    const float4* s = (const float4*)(src + (size_t)r * ld + c8);
    float4 v0 = s[0], v1 = s[1];
    float vv[8] = {v0.x, v0.y, v0.z, v0.w, v1.x, v1.y, v1.z, v1.w};
    __nv_bfloat16 H[8], L[8];
#pragma unroll
    for (int j = 0; j < 8; j++) split2(vv[j], H[j], L[j]);

    uint32_t w[12];
#pragma unroll
    for (int p = 0; p < 4; p++) {
        int e = 2*p, o = 2*p + 1;
        if (ASIDE) {
            w[3*p+0] = pk(H[e], H[e]);
            w[3*p+1] = pk(L[e], H[o]);
            w[3*p+2] = pk(H[o], L[o]);
        } else {
            w[3*p+0] = pk(H[e], L[e]);
            w[3*p+1] = pk(H[e], H[o]);
            w[3*p+2] = pk(L[o], H[o]);
        }
    }
    uint4* out = (uint4*)(dst + (size_t)r * 3 * cols + 3 * c8);
    out[0] = make_uint4(w[0], w[1], w[2],  w[3]);
    out[1] = make_uint4(w[4], w[5], w[6],  w[7]);
    out[2] = make_uint4(w[8], w[9], w[10], w[11]);
}

// fp16 hi-dup weight quad: per k -> [hi, hi]
__device__ __forceinline__ void splitf16_dup_quad(const float* __restrict__ src,
                                                  int ld, int cols,
                                                  __half* __restrict__ dst, int q)
{
    int qpr = cols >> 3;
    int r = q / qpr;
    int c8 = (q - r * qpr) << 3;
    const float4* s = (const float4*)(src + (size_t)r * ld + c8);
    float4 v0 = s[0], v1 = s[1];
    float vv[8] = {v0.x, v0.y, v0.z, v0.w, v1.x, v1.y, v1.z, v1.w};
    uint32_t w[8];
#pragma unroll
    for (int j = 0; j < 8; j++) {
        __half h = __float2half_rn(vv[j]);
        w[j] = pkh(h, h);
    }
    uint4* out = (uint4*)(dst + (size_t)r * 2 * cols + 2 * c8);
    out[0] = make_uint4(w[0], w[1], w[2], w[3]);
    out[1] = make_uint4(w[4], w[5], w[6], w[7]);
}

// ---- ONE mega split launch ----
#define WIN_Q  ((2*DMODEL)*DMODEL/8)
#define WXP_Q  (XDBL_W*DMODEL/8)
#define WDT_Q  (DMODEL*DTRANK/8)
#define WOUT_Q (DMODEL*DMODEL/8)
#define X_Q    (MROWS*DMODEL/8)
#define ALL_Q  (WIN_Q+WXP_Q+WDT_Q+WOUT_Q+X_Q)

__global__ void __launch_bounds__(256)
mega_split_kernel(const float* __restrict__ W_in,
                  const float* __restrict__ W_xproj,
                  const float* __restrict__ W_dt,
                  const float* __restrict__ W_out,
                  const float* __restrict__ x,
                  __nv_bfloat16* __restrict__ wih3,
                  __nv_bfloat16* __restrict__ wxh3,
                  __nv_bfloat16* __restrict__ wdt3,
                  __half* __restrict__ woh2,
                  __nv_bfloat16* __restrict__ xh3)
{
    int q = blockIdx.x * blockDim.x + threadIdx.x;
    if (q < WIN_Q)  { split3_quad<0>(W_in,   DMODEL, DMODEL, wih3, q); return; }
    q -= WIN_Q;
    if (q < WXP_Q)  { split3_quad<0>(W_xproj, DMODEL, DMODEL, wxh3, q); return; }
    q -= WXP_Q;
    if (q < WDT_Q)  { split3_quad<0>(W_dt,   DTRANK, DTRANK, wdt3, q); return; }
    q -= WDT_Q;
    if (q < WOUT_Q) { splitf16_dup_quad(W_out, DMODEL, DMODEL, woh2, q); return; }
    q -= WOUT_Q;
    if (q < X_Q)      split3_quad<1>(x,      DMODEL, DMODEL, xh3,  q);
}

// ---------------- tensor-core GEMM: 3-stage cp.async (bf16 or fp16) --------
#define STG   32768
#define GSMEM (3*STG)

template<int EPI, int F16>
__global__ void __launch_bounds__(256, 2)
gemm_mma(const void* __restrict__ Av,
         const void* __restrict__ Bv,
         float* __restrict__ C, int ldc,
         int Nb, int Kstride, int Klen, size_t cslab,
         const float* __restrict__ bias)
{
    const __nv_bfloat16* A = (const __nv_bfloat16*)Av;  // element size 2 either way
    const __nv_bfloat16* B = (const __nv_bfloat16*)Bv;
    extern __shared__ __align__(1024) char smem[];
    const uint32_t sbase = smem_u32(smem);

    const int tid  = threadIdx.x;
    const int wid  = tid >> 5;
    const int lane = tid & 31;
    const int m0 = blockIdx.y << 7;
    const int n0 = blockIdx.x << 7;
    const int koff = blockIdx.z * Klen;
    C += (size_t)blockIdx.z * cslab;

    const int wm = (wid & 1) * 64;
    const int wn = (wid >> 1) * 32;
    const int nch = Klen >> 6;

    const int lrow = tid >> 3;
    const int lch  = tid & 7;
    auto load_stage = [&](uint32_t sA, int i) {
        const int k0 = koff + (i << 6);
        const uint32_t sB = sA + 16384;
#pragma unroll
        for (int j = 0; j < 4; j++) {
            int row = lrow + j * 32;
            uint32_t so = (uint32_t)(row * 128 + ((lch ^ (row & 7)) << 4));
            cp_async16(sA + so, A + (size_t)(m0 + row) * Kstride + k0 + lch * 8, 16);
            int n = n0 + row;
            int nc = (n < Nb) ? n : (Nb - 1);
            cp_async16(sB + so, B + (size_t)nc * Kstride + k0 + lch * 8,
                       (n < Nb) ? 16 : 0);
        }
    };

    float acc[4][4][4];
#pragma unroll
    for (int i = 0; i < 4; i++)
#pragma unroll
        for (int j = 0; j < 4; j++)
#pragma unroll
            for (int e = 0; e < 4; e++) acc[i][j][e] = 0.f;

    const int a_r = lane & 15;
    const int a_c = lane >> 4;
    const int b_r = ((lane >> 4) & 1) * 8 + (lane & 7);
    const int b_c = (lane >> 3) & 1;

    uint32_t buf0 = sbase, buf1 = sbase + STG, buf2 = sbase + 2*STG;

    load_stage(buf0, 0); CP_COMMIT();
    if (nch > 1) load_stage(buf1, 1);
    CP_COMMIT();

    for (int i = 0; i < nch; i++) {
        CP_WAIT1();
        __syncthreads();
        if (i + 2 < nch) load_stage(buf2, i + 2);
        CP_COMMIT();

        const uint32_t sA = buf0;
        const uint32_t sB = buf0 + 16384;
#pragma unroll
        for (int ks = 0; ks < 4; ks++) {
            uint32_t af[4][4], bf4[2][4];
#pragma unroll
            for (int mi = 0; mi < 4; mi++) {
                int row = wm + mi * 16 + a_r;
                int ch  = ks * 2 + a_c;
                ldsm_x4(af[mi], sA + row * 128 + ((ch ^ (row & 7)) << 4));
            }
#pragma unroll
            for (int nj = 0; nj < 2; nj++) {
                int row = wn + nj * 16 + b_r;
                int ch  = ks * 2 + b_c;
                ldsm_x4(bf4[nj], sB + row * 128 + ((ch ^ (row & 7)) << 4));
            }
#pragma unroll
            for (int mi = 0; mi < 4; mi++)
#pragma unroll
                for (int ni = 0; ni < 4; ni++)
                    mma16816<F16>(acc[mi][ni], af[mi], &bf4[ni >> 1][(ni & 1) * 2]);
        }
        uint32_t t = buf0; buf0 = buf1; buf1 = buf2; buf2 = t;
    }

    const int er = lane >> 2;
    const int ec = (lane & 3) * 2;
#pragma unroll
    for (int mi = 0; mi < 4; mi++) {
#pragma unroll
        for (int half = 0; half < 2; half++) {
            int m = m0 + wm + mi * 16 + er + half * 8;
            float* crow = C + (size_t)m * ldc;
#pragma unroll
            for (int ni = 0; ni < 4; ni++) {
                int n = n0 + wn + ni * 8 + ec;
                float v0 = acc[mi][ni][half * 2 + 0];
                float v1 = acc[mi][ni][half * 2 + 1];
                if (EPI == 1) {
                    v0 += bias[n];     v1 += bias[n + 1];
                    v0 = (v0 > 20.f) ? v0 : log1pf(expf(v0));
                    v1 = (v1 > 20.f) ? v1 : log1pf(expf(v1));
                }
                *(float2*)&crow[n] = make_float2(v0, v1);
            }
        }
    }
}

// ---------------- xproj split-K reduce + fused dt-rank split ----------------
__global__ void __launch_bounds__(256)
reduce_xproj(const float* __restrict__ part,
             float* __restrict__ xdbl,
             __nv_bfloat16* __restrict__ dta3)
{
    int idx = blockIdx.x * blockDim.x + threadIdx.x;
    if (idx >= MROWS * XDBL_W) return;
    int m = idx / XDBL_W;
    int n = idx - m * XDBL_W;
    float s = 0.f;
#pragma unroll
    for (int z = 0; z < NSPLITK; z++)
        s += part[(size_t)z * MROWS * XP_LD + (size_t)m * XP_LD + n];
    xdbl[idx] = s;
    if (n < DTRANK) {
        __nv_bfloat16 h, l; split2(s, h, l);
        __nv_bfloat16* o = dta3 + (size_t)m * K3DT + 3 * n;
        o[0] = h; o[1] = h; o[2] = l;
    }
}

// ---------------- conv(K=4) + SiLU + fused A-side split (4 l per thread) ---
__global__ void __launch_bounds__(256)
conv_silu_split(const float* __restrict__ xz,
                const float* __restrict__ conv_w,
                const float* __restrict__ conv_b,
                float* __restrict__ u,
                __nv_bfloat16* __restrict__ uh3)
{
    int idx = blockIdx.x * blockDim.x + threadIdx.x;
    if (idx >= MROWS * DMODEL / 4) return;
    int d = idx & (DMODEL - 1);
    int t = idx >> 11;
    int l0 = (t & 255) << 2;
    int b  = t >> 8;

    float w0 = conv_w[d*4+0], w1 = conv_w[d*4+1],
          w2 = conv_w[d*4+2], w3 = conv_w[d*4+3];
    float cb = conv_b[d];

    size_t base = (size_t)(b * SEQ) * (2*DMODEL) + d;
    float v[7];
#pragma unroll
    for (int j = 0; j < 7; j++) {
        int l = l0 - 3 + j;
        v[j] = (l >= 0) ? xz[base + (size_t)l * (2*DMODEL)] : 0.f;
    }
#pragma unroll
    for (int k = 0; k < 4; k++) {
        float acc = cb + w0*v[k] + w1*v[k+1] + w2*v[k+2] + w3*v[k+3];
        float sig = 1.f / (1.f + __expf(-acc));
        float val = acc * sig;
        int m = b * SEQ + l0 + k;
        u[(size_t)m * DMODEL + d] = val;
        __nv_bfloat16 h, lo; split2(val, h, lo);
        __nv_bfloat16* o = uh3 + (size_t)m * K3 + 3 * d;
        o[0] = h; o[1] = h; o[2] = lo;
    }
}

// ---------------- selective scan + gate + fused fp16 2-term split ----------
#define DG 16
#define CL 64
__global__ void __launch_bounds__(256)
scan_kernel(const float* __restrict__ xdbl,
            const float* __restrict__ dt,
            const float* __restrict__ u,
            const float* __restrict__ xz,
            const float* __restrict__ A_log,
            const float* __restrict__ Dskip,
            __half* __restrict__ yph2)
{
    const int b    = blockIdx.x >> 7;
    const int dblk = blockIdx.x & 127;
    const int d0   = dblk * DG;
    const int tid  = threadIdx.x;
    const int dloc = tid >> 4;
    const int n    = tid & 15;
    const int d    = d0 + dloc;

    const float Adn = -expf(A_log[d * DSTATE + n]);
    const float Dsk = Dskip[d];
    float h = 0.f;

    __shared__ float sdt[CL*DG], su[CL*DG], sz[CL*DG];
    __shared__ float sB[CL*DSTATE], sC[CL*DSTATE];

    for (int c = 0; c < SEQ / CL; c++) {
        const int l0 = c * CL;
        __syncthreads();
#pragma unroll
        for (int e = tid; e < CL*DG; e += 256) {
            int lr = e >> 4, el = e & 15;
            size_t row = (size_t)(b * SEQ + l0 + lr);
            sdt[e] = dt[row * DMODEL + d0 + el];
            su[e]  = u [row * DMODEL + d0 + el];
            sz[e]  = xz[row * (2*DMODEL) + DMODEL + d0 + el];
            sB[e]  = xdbl[row * XDBL_W + DTRANK + el];
            sC[e]  = xdbl[row * XDBL_W + DTRANK + DSTATE + el];
        }
        __syncthreads();

#pragma unroll 8
        for (int lr = 0; lr < CL; lr++) {
            float dtv = sdt[lr*16 + dloc];
            float uu  = su [lr*16 + dloc];
            float dA  = __expf(dtv * Adn);
            h = dA * h + (dtv * uu) * sB[lr*16 + n];
            float y = h * sC[lr*16 + n];
            y += __shfl_xor_sync(0xffffffffu, y, 8, 16);
            y += __shfl_xor_sync(0xffffffffu, y, 4, 16);
            y += __shfl_xor_sync(0xffffffffu, y, 2, 16);
            y += __shfl_xor_sync(0xffffffffu, y, 1, 16);
            if (n == 0) {
                float z   = sz[lr*16 + dloc];
                float sig = 1.f / (1.f + __expf(-z));
                float val = (y + uu * Dsk) * (z * sig);
                __half hh = __float2half_rn(val);
                __half ll = __float2half_rn(val - __half2float(hh));
                __half* o = yph2 +
                    (size_t)(b * SEQ + l0 + lr) * K2OUT + 2 * d;
                o[0] = hh; o[1] = ll;
            }
        }
    }
}

// ---------------- launch ----------------
extern "C" void kernel_launch(void* const* d_in, const int* in_sizes, int n_in,
                              void* d_out, int out_size)
{
    const float* x      = (const float*)d_in[0];
    const float* W_in   = (const float*)d_in[1];
    const float* conv_w = (const float*)d_in[2];
    const float* conv_b = (const float*)d_in[3];
    const float* W_xproj= (const float*)d_in[4];
    const float* W_dt   = (const float*)d_in[5];
    const float* b_dt   = (const float*)d_in[6];
    const float* A_log  = (const float*)d_in[7];
    const float* Dskip  = (const float*)d_in[8];
    const float* W_out  = (const float*)d_in[9];
    float* out = (float*)d_out;

    float *xz, *u, *xdbl, *dtb, *part;
    __nv_bfloat16 *xh3, *wih3, *uh3, *wxh3, *dta3, *wdt3;
    __half *yph2, *woh2;
    cudaGetSymbolAddress((void**)&xz,   g_xz);
    cudaGetSymbolAddress((void**)&u,    g_u);
    cudaGetSymbolAddress((void**)&xdbl, g_xdbl);
    cudaGetSymbolAddress((void**)&dtb,  g_dt);
    cudaGetSymbolAddress((void**)&part, g_part);
    cudaGetSymbolAddress((void**)&xh3,  g_xh3);
    cudaGetSymbolAddress((void**)&wih3, g_wih3);
    cudaGetSymbolAddress((void**)&uh3,  g_uh3);
    cudaGetSymbolAddress((void**)&wxh3, g_wxh3);
    cudaGetSymbolAddress((void**)&dta3, g_dta3);
    cudaGetSymbolAddress((void**)&wdt3, g_wdt3);
    cudaGetSymbolAddress((void**)&yph2, g_yph2);
    cudaGetSymbolAddress((void**)&woh2, g_woh2);

    cudaFuncSetAttribute((const void*)gemm_mma<0,0>, cudaFuncAttributeMaxDynamicSharedMemorySize, GSMEM);
    cudaFuncSetAttribute((const void*)gemm_mma<1,0>, cudaFuncAttributeMaxDynamicSharedMemorySize, GSMEM);
    cudaFuncSetAttribute((const void*)gemm_mma<0,1>, cudaFuncAttributeMaxDynamicSharedMemorySize, GSMEM);

    // --- 0) one mega split launch: all weights + x ---
    mega_split_kernel<<<(ALL_Q + 255)/256, 256>>>(
        W_in, W_xproj, W_dt, W_out, x, wih3, wxh3, wdt3, woh2, xh3);

    // --- 1) xz = x @ W_in^T (bf16x3) ---
    {
        dim3 grid((2*DMODEL)/128, MROWS/128, 1);
        gemm_mma<0,0><<<grid, 256, GSMEM>>>(xh3, wih3, xz, 2*DMODEL,
                                            2*DMODEL, K3, K3, 0, nullptr);
    }
    // --- 2) u = silu(conv(xz[:, :2048])), fused bf16x3 split ---
    {
        int total = MROWS * DMODEL / 4;
        conv_silu_split<<<(total + 255)/256, 256>>>(xz, conv_w, conv_b, u, uh3);
    }
    // --- 3) x_dbl = u @ W_xproj^T  (split-K x8, bf16x3) ---
    {
        dim3 grid(2, MROWS/128, NSPLITK);
        gemm_mma<0,0><<<grid, 256, GSMEM>>>(uh3, wxh3, part, XP_LD,
                                            XDBL_W, K3, K3/NSPLITK,
                                            (size_t)MROWS * XP_LD, nullptr);
        int tot = MROWS * XDBL_W;
        reduce_xproj<<<(tot+255)/256, 256>>>(part, xdbl, dta3);
    }
    // --- 4) dt = softplus(x_dbl[:, :128] @ W_dt^T + b_dt) (bf16x3) ---
    {
        dim3 grid(DMODEL/128, MROWS/128, 1);
        gemm_mma<1,0><<<grid, 256, GSMEM>>>(dta3, wdt3, dtb, DMODEL,
                                            DMODEL, K3DT, K3DT, 0, b_dt);
    }
    // --- 5) selective scan + gate, fused fp16 2-term split ---
    scan_kernel<<<BSZ * (DMODEL/DG), 256>>>(xdbl, dtb, u, xz, A_log, Dskip, yph2);
    // --- 6) out = ypre @ W_out^T  (fp16 2-term: 33% less work) ---
    {
        dim3 grid(DMODEL/128, MROWS/128, 1);
        gemm_mma<0,1><<<grid, 256, GSMEM>>>(yph2, woh2, out, DMODEL,
                                            DMODEL, K2OUT, K2OUT, 0, nullptr);
    }
}

// round 9
// speedup vs baseline: 1.4025x; 1.1562x over previous
#include <cuda_runtime.h>
#include <cuda_bf16.h>
#include <cuda_fp16.h>
#include <cstdint>

// ---------------- problem constants ----------------
#define DMODEL 2048
#define DSTATE 16
#define DTRANK 128
#define BSZ    2
#define SEQ    1024
#define MROWS  (BSZ*SEQ)            // 2048
#define XDBL_W (DTRANK + 2*DSTATE)  // 160
#define K3     (3*DMODEL)           // 6144 (bf16x3 expanded K)
#define K3DT   (3*DTRANK)           // 384
#define K2     (2*DMODEL)           // 4096 (fp16 2-term expanded K)
#define NSPLITK 8
#define XP_LD   256

// ---------------- static scratch ----------------
__device__ float g_xz  [(size_t)MROWS * (2*DMODEL)];
__device__ float g_u   [(size_t)MROWS * DMODEL];
__device__ float g_xdbl[(size_t)MROWS * XDBL_W];
__device__ float g_dt  [(size_t)MROWS * DMODEL];
__device__ float g_part[(size_t)NSPLITK * MROWS * XP_LD];

__device__ __half        g_xh2 [(size_t)MROWS  * K2];      // fp16 2-term x
__device__ __half        g_wih2[(size_t)(2*DMODEL) * K2];  // fp16 hi-dup W_in
__device__ __nv_bfloat16 g_uh3 [(size_t)MROWS  * K3];
__device__ __nv_bfloat16 g_wxh3[(size_t)XDBL_W * K3];
__device__ __nv_bfloat16 g_dta3[(size_t)MROWS  * K3DT];
__device__ __nv_bfloat16 g_wdt3[(size_t)DMODEL * K3DT];
__device__ __half        g_yph2[(size_t)MROWS  * K2];      // fp16 2-term ypre
__device__ __half        g_woh2[(size_t)DMODEL * K2];      // fp16 hi-dup W_out

// ---------------- PTX helpers ----------------
__device__ __forceinline__ uint32_t smem_u32(const void* p) {
    uint32_t a;
    asm("{ .reg .u64 t; cvta.to.shared.u64 t, %1; cvt.u32.u64 %0, t; }" : "=r"(a) : "l"(p));
    return a;
}
__device__ __forceinline__ void cp_async16(uint32_t saddr, const void* gaddr, int src_bytes) {
    asm volatile("cp.async.cg.shared.global [%0], [%1], 16, %2;"
                 :: "r"(saddr), "l"(gaddr), "r"(src_bytes) : "memory");
}
#define CP_COMMIT() asm volatile("cp.async.commit_group;" ::: "memory")
#define CP_WAIT1()  asm volatile("cp.async.wait_group 1;" ::: "memory")

__device__ __forceinline__ void ldsm_x4(uint32_t* r, uint32_t addr) {
    asm volatile("ldmatrix.sync.aligned.m8n8.x4.shared.b16 {%0,%1,%2,%3}, [%4];"
                 : "=r"(r[0]), "=r"(r[1]), "=r"(r[2]), "=r"(r[3]) : "r"(addr));
}
template<int F16>
__device__ __forceinline__ void mma16816(float* d, const uint32_t* a, const uint32_t* b) {
    if (F16)
        asm volatile(
            "mma.sync.aligned.m16n8k16.row.col.f32.f16.f16.f32 "
            "{%0,%1,%2,%3}, {%4,%5,%6,%7}, {%8,%9}, {%0,%1,%2,%3};"
            : "+f"(d[0]), "+f"(d[1]), "+f"(d[2]), "+f"(d[3])
            : "r"(a[0]), "r"(a[1]), "r"(a[2]), "r"(a[3]), "r"(b[0]), "r"(b[1]));
    else
        asm volatile(
            "mma.sync.aligned.m16n8k16.row.col.f32.bf16.bf16.f32 "
            "{%0,%1,%2,%3}, {%4,%5,%6,%7}, {%8,%9}, {%0,%1,%2,%3};"
            : "+f"(d[0]), "+f"(d[1]), "+f"(d[2]), "+f"(d[3])
            : "r"(a[0]), "r"(a[1]), "r"(a[2]), "r"(a[3]), "r"(b[0]), "r"(b[1]));
}
__device__ __forceinline__ void split2(float v, __nv_bfloat16& h, __nv_bfloat16& l) {
    h = __float2bfloat16(v);
    l = __float2bfloat16(v - __bfloat162float(h));
}
__device__ __forceinline__ uint32_t pk(__nv_bfloat16 a, __nv_bfloat16 b) {
    __nv_bfloat162 t; t.x = a; t.y = b;
    uint32_t r; *(__nv_bfloat162*)&r = t; return r;
}
__device__ __forceinline__ uint32_t pkh(__half a, __half b) {
    __half2 t; t.x = a; t.y = b;
    uint32_t r; *(__half2*)&r = t; return r;
}

// ---------------- vectorized bf16x3 split quads ----------------
template<int ASIDE>
__device__ __forceinline__ void split3_quad(const float* __restrict__ src,
                                            int ld, int cols,
                                            __nv_bfloat16* __restrict__ dst, int q)
{
    int qpr = cols >> 3;
    int r = q / qpr;
    int c8 = (q - r * qpr) << 3;
    const float4* s = (const float4*)(src + (size_t)r * ld + c8);
    float4 v0 = s[0], v1 = s[1];
    float vv[8] = {v0.x, v0.y, v0.z, v0.w, v1.x, v1.y, v1.z, v1.w};
    __nv_bfloat16 H[8], L[8];
#pragma unroll
    for (int j = 0; j < 8; j++) split2(vv[j], H[j], L[j]);

    uint32_t w[12];
#pragma unroll
    for (int p = 0; p < 4; p++) {
        int e = 2*p, o = 2*p + 1;
        if (ASIDE) {
            w[3*p+0] = pk(H[e], H[e]);
            w[3*p+1] = pk(L[e], H[o]);
            w[3*p+2] = pk(H[o], L[o]);
        } else {
            w[3*p+0] = pk(H[e], L[e]);
            w[3*p+1] = pk(H[e], H[o]);
            w[3*p+2] = pk(L[o], H[o]);
        }
    }
    uint4* out = (uint4*)(dst + (size_t)r * 3 * cols + 3 * c8);
    out[0] = make_uint4(w[0], w[1], w[2],  w[3]);
    out[1] = make_uint4(w[4], w[5], w[6],  w[7]);
    out[2] = make_uint4(w[8], w[9], w[10], w[11]);
}

// fp16 hi-dup weight quad: per k -> [hi, hi]
__device__ __forceinline__ void splitf16_dup_quad(const float* __restrict__ src,
                                                  int ld, int cols,
                                                  __half* __restrict__ dst, int q)
{
    int qpr = cols >> 3;
    int r = q / qpr;
    int c8 = (q - r * qpr) << 3;
    const float4* s = (const float4*)(src + (size_t)r * ld + c8);
    float4 v0 = s[0], v1 = s[1];
    float vv[8] = {v0.x, v0.y, v0.z, v0.w, v1.x, v1.y, v1.z, v1.w};
    uint32_t w[8];
#pragma unroll
    for (int j = 0; j < 8; j++) {
        __half h = __float2half_rn(vv[j]);
        w[j] = pkh(h, h);
    }
    uint4* out = (uint4*)(dst + (size_t)r * 2 * cols + 2 * c8);
    out[0] = make_uint4(w[0], w[1], w[2], w[3]);
    out[1] = make_uint4(w[4], w[5], w[6], w[7]);
}

// fp16 2-term A-side quad: per k -> [hi, lo]
__device__ __forceinline__ void splitf16_a2_quad(const float* __restrict__ src,
                                                 int ld, int cols,
                                                 __half* __restrict__ dst, int q)
{
    int qpr = cols >> 3;
    int r = q / qpr;
    int c8 = (q - r * qpr) << 3;
    const float4* s = (const float4*)(src + (size_t)r * ld + c8);
    float4 v0 = s[0], v1 = s[1];
    float vv[8] = {v0.x, v0.y, v0.z, v0.w, v1.x, v1.y, v1.z, v1.w};
    uint32_t w[8];
#pragma unroll
    for (int j = 0; j < 8; j++) {
        __half h = __float2half_rn(vv[j]);
        __half l = __float2half_rn(vv[j] - __half2float(h));
        w[j] = pkh(h, l);
    }
    uint4* out = (uint4*)(dst + (size_t)r * 2 * cols + 2 * c8);
    out[0] = make_uint4(w[0], w[1], w[2], w[3]);
    out[1] = make_uint4(w[4], w[5], w[6], w[7]);
}

// ---- ONE mega split launch ----
#define WIN_Q  ((2*DMODEL)*DMODEL/8)
#define WXP_Q  (XDBL_W*DMODEL/8)
#define WDT_Q  (DMODEL*DTRANK/8)
#define WOUT_Q (DMODEL*DMODEL/8)
#define X_Q    (MROWS*DMODEL/8)
#define ALL_Q  (WIN_Q+WXP_Q+WDT_Q+WOUT_Q+X_Q)

__global__ void __launch_bounds__(256)
mega_split_kernel(const float* __restrict__ W_in,
                  const float* __restrict__ W_xproj,
                  const float* __restrict__ W_dt,
                  const float* __restrict__ W_out,
                  const float* __restrict__ x,
                  __half* __restrict__ wih2,
                  __nv_bfloat16* __restrict__ wxh3,
                  __nv_bfloat16* __restrict__ wdt3,
                  __half* __restrict__ woh2,
                  __half* __restrict__ xh2)
{
    int q = blockIdx.x * blockDim.x + threadIdx.x;
    if (q < WIN_Q)  { splitf16_dup_quad(W_in, DMODEL, DMODEL, wih2, q); return; }
    q -= WIN_Q;
    if (q < WXP_Q)  { split3_quad<0>(W_xproj, DMODEL, DMODEL, wxh3, q); return; }
    q -= WXP_Q;
    if (q < WDT_Q)  { split3_quad<0>(W_dt,   DTRANK, DTRANK, wdt3, q); return; }
    q -= WDT_Q;
    if (q < WOUT_Q) { splitf16_dup_quad(W_out, DMODEL, DMODEL, woh2, q); return; }
    q -= WOUT_Q;
    if (q < X_Q)      splitf16_a2_quad(x,     DMODEL, DMODEL, xh2,  q);
}

// ---------------- tensor-core GEMM: 3-stage cp.async (bf16 or fp16) --------
#define STG   32768
#define GSMEM (3*STG)

template<int EPI, int F16>
__global__ void __launch_bounds__(256, 2)
gemm_mma(const void* __restrict__ Av,
         const void* __restrict__ Bv,
         float* __restrict__ C, int ldc,
         int Nb, int Kstride, int Klen, size_t cslab,
         const float* __restrict__ bias)
{
    const __nv_bfloat16* A = (const __nv_bfloat16*)Av;  // 2-byte elements either way
    const __nv_bfloat16* B = (const __nv_bfloat16*)Bv;
    extern __shared__ __align__(1024) char smem[];
    const uint32_t sbase = smem_u32(smem);

    const int tid  = threadIdx.x;
    const int wid  = tid >> 5;
    const int lane = tid & 31;
    const int m0 = blockIdx.y << 7;
    const int n0 = blockIdx.x << 7;
    const int koff = blockIdx.z * Klen;
    C += (size_t)blockIdx.z * cslab;

    const int wm = (wid & 1) * 64;
    const int wn = (wid >> 1) * 32;
    const int nch = Klen >> 6;

    const int lrow = tid >> 3;
    const int lch  = tid & 7;
    auto load_stage = [&](uint32_t sA, int i) {
        const int k0 = koff + (i << 6);
        const uint32_t sB = sA + 16384;
#pragma unroll
        for (int j = 0; j < 4; j++) {
            int row = lrow + j * 32;
            uint32_t so = (uint32_t)(row * 128 + ((lch ^ (row & 7)) << 4));
            cp_async16(sA + so, A + (size_t)(m0 + row) * Kstride + k0 + lch * 8, 16);
            int n = n0 + row;
            int nc = (n < Nb) ? n : (Nb - 1);
            cp_async16(sB + so, B + (size_t)nc * Kstride + k0 + lch * 8,
                       (n < Nb) ? 16 : 0);
        }
    };

    float acc[4][4][4];
#pragma unroll
    for (int i = 0; i < 4; i++)
#pragma unroll
        for (int j = 0; j < 4; j++)
#pragma unroll
            for (int e = 0; e < 4; e++) acc[i][j][e] = 0.f;

    const int a_r = lane & 15;
    const int a_c = lane >> 4;
    const int b_r = ((lane >> 4) & 1) * 8 + (lane & 7);
    const int b_c = (lane >> 3) & 1;

    uint32_t buf0 = sbase, buf1 = sbase + STG, buf2 = sbase + 2*STG;

    load_stage(buf0, 0); CP_COMMIT();
    if (nch > 1) load_stage(buf1, 1);
    CP_COMMIT();

    for (int i = 0; i < nch; i++) {
        CP_WAIT1();
        __syncthreads();
        if (i + 2 < nch) load_stage(buf2, i + 2);
        CP_COMMIT();

        const uint32_t sA = buf0;
        const uint32_t sB = buf0 + 16384;
#pragma unroll
        for (int ks = 0; ks < 4; ks++) {
            uint32_t af[4][4], bf4[2][4];
#pragma unroll
            for (int mi = 0; mi < 4; mi++) {
                int row = wm + mi * 16 + a_r;
                int ch  = ks * 2 + a_c;
                ldsm_x4(af[mi], sA + row * 128 + ((ch ^ (row & 7)) << 4));
            }
#pragma unroll
            for (int nj = 0; nj < 2; nj++) {
                int row = wn + nj * 16 + b_r;
                int ch  = ks * 2 + b_c;
                ldsm_x4(bf4[nj], sB + row * 128 + ((ch ^ (row & 7)) << 4));
            }
#pragma unroll
            for (int mi = 0; mi < 4; mi++)
#pragma unroll
                for (int ni = 0; ni < 4; ni++)
                    mma16816<F16>(acc[mi][ni], af[mi], &bf4[ni >> 1][(ni & 1) * 2]);
        }
        uint32_t t = buf0; buf0 = buf1; buf1 = buf2; buf2 = t;
    }

    const int er = lane >> 2;
    const int ec = (lane & 3) * 2;
#pragma unroll
    for (int mi = 0; mi < 4; mi++) {
#pragma unroll
        for (int half = 0; half < 2; half++) {
            int m = m0 + wm + mi * 16 + er + half * 8;
            float* crow = C + (size_t)m * ldc;
#pragma unroll
            for (int ni = 0; ni < 4; ni++) {
                int n = n0 + wn + ni * 8 + ec;
                float v0 = acc[mi][ni][half * 2 + 0];
                float v1 = acc[mi][ni][half * 2 + 1];
                if (EPI == 1) {
                    v0 += bias[n];     v1 += bias[n + 1];
                    v0 = (v0 > 20.f) ? v0 : log1pf(expf(v0));
                    v1 = (v1 > 20.f) ? v1 : log1pf(expf(v1));
                }
                *(float2*)&crow[n] = make_float2(v0, v1);
            }
        }
    }
}

// ---------------- xproj split-K reduce + fused dt-rank split ----------------
__global__ void __launch_bounds__(256)
reduce_xproj(const float* __restrict__ part,
             float* __restrict__ xdbl,
             __nv_bfloat16* __restrict__ dta3)
{
    int idx = blockIdx.x * blockDim.x + threadIdx.x;
    if (idx >= MROWS * XDBL_W) return;
    int m = idx / XDBL_W;
    int n = idx - m * XDBL_W;
    float s = 0.f;
#pragma unroll
    for (int z = 0; z < NSPLITK; z++)
        s += part[(size_t)z * MROWS * XP_LD + (size_t)m * XP_LD + n];
    xdbl[idx] = s;
    if (n < DTRANK) {
        __nv_bfloat16 h, l; split2(s, h, l);
        __nv_bfloat16* o = dta3 + (size_t)m * K3DT + 3 * n;
        o[0] = h; o[1] = h; o[2] = l;
    }
}

// ---------------- conv(K=4) + SiLU + fused A-side split (4 l per thread) ---
__global__ void __launch_bounds__(256)
conv_silu_split(const float* __restrict__ xz,
                const float* __restrict__ conv_w,
                const float* __restrict__ conv_b,
                float* __restrict__ u,
                __nv_bfloat16* __restrict__ uh3)
{
    int idx = blockIdx.x * blockDim.x + threadIdx.x;
    if (idx >= MROWS * DMODEL / 4) return;
    int d = idx & (DMODEL - 1);
    int t = idx >> 11;
    int l0 = (t & 255) << 2;
    int b  = t >> 8;

    float w0 = conv_w[d*4+0], w1 = conv_w[d*4+1],
          w2 = conv_w[d*4+2], w3 = conv_w[d*4+3];
    float cb = conv_b[d];

    size_t base = (size_t)(b * SEQ) * (2*DMODEL) + d;
    float v[7];
#pragma unroll
    for (int j = 0; j < 7; j++) {
        int l = l0 - 3 + j;
        v[j] = (l >= 0) ? xz[base + (size_t)l * (2*DMODEL)] : 0.f;
    }
#pragma unroll
    for (int k = 0; k < 4; k++) {
        float acc = cb + w0*v[k] + w1*v[k+1] + w2*v[k+2] + w3*v[k+3];
        float sig = 1.f / (1.f + __expf(-acc));
        float val = acc * sig;
        int m = b * SEQ + l0 + k;
        u[(size_t)m * DMODEL + d] = val;
        __nv_bfloat16 h, lo; split2(val, h, lo);
        __nv_bfloat16* o = uh3 + (size_t)m * K3 + 3 * d;
        o[0] = h; o[1] = h; o[2] = lo;
    }
}

// ---------------- selective scan + gate + fused fp16 2-term split ----------
#define DG 16
#define CL 64
__global__ void __launch_bounds__(256)
scan_kernel(const float* __restrict__ xdbl,
            const float* __restrict__ dt,
            const float* __restrict__ u,
            const float* __restrict__ xz,
            const float* __restrict__ A_log,
            const float* __restrict__ Dskip,
            __half* __restrict__ yph2)
{
    const int b    = blockIdx.x >> 7;
    const int dblk = blockIdx.x & 127;
    const int d0   = dblk * DG;
    const int tid  = threadIdx.x;
    const int dloc = tid >> 4;
    const int n    = tid & 15;
    const int d    = d0 + dloc;

    const float Adn = -expf(A_log[d * DSTATE + n]);
    const float Dsk = Dskip[d];
    float h = 0.f;

    __shared__ float sdt[CL*DG], su[CL*DG], sz[CL*DG];
    __shared__ float sB[CL*DSTATE], sC[CL*DSTATE];

    for (int c = 0; c < SEQ / CL; c++) {
        const int l0 = c * CL;
        __syncthreads();
#pragma unroll
        for (int e = tid; e < CL*DG; e += 256) {
            int lr = e >> 4, el = e & 15;
            size_t row = (size_t)(b * SEQ + l0 + lr);
            sdt[e] = dt[row * DMODEL + d0 + el];
            su[e]  = u [row * DMODEL + d0 + el];
            sz[e]  = xz[row * (2*DMODEL) + DMODEL + d0 + el];
            sB[e]  = xdbl[row * XDBL_W + DTRANK + el];
            sC[e]  = xdbl[row * XDBL_W + DTRANK + DSTATE + el];
        }
        __syncthreads();

#pragma unroll 8
        for (int lr = 0; lr < CL; lr++) {
            float dtv = sdt[lr*16 + dloc];
            float uu  = su [lr*16 + dloc];
            float dA  = __expf(dtv * Adn);
            h = dA * h + (dtv * uu) * sB[lr*16 + n];
            float y = h * sC[lr*16 + n];
            y += __shfl_xor_sync(0xffffffffu, y, 8, 16);
            y += __shfl_xor_sync(0xffffffffu, y, 4, 16);
            y += __shfl_xor_sync(0xffffffffu, y, 2, 16);
            y += __shfl_xor_sync(0xffffffffu, y, 1, 16);
            if (n == 0) {
                float z   = sz[lr*16 + dloc];
                float sig = 1.f / (1.f + __expf(-z));
                float val = (y + uu * Dsk) * (z * sig);
                __half hh = __float2half_rn(val);
                __half ll = __float2half_rn(val - __half2float(hh));
                __half* o = yph2 +
                    (size_t)(b * SEQ + l0 + lr) * K2 + 2 * d;
                o[0] = hh; o[1] = ll;
            }
        }
    }
}

// ---------------- launch ----------------
extern "C" void kernel_launch(void* const* d_in, const int* in_sizes, int n_in,
                              void* d_out, int out_size)
{
    const float* x      = (const float*)d_in[0];
    const float* W_in   = (const float*)d_in[1];
    const float* conv_w = (const float*)d_in[2];
    const float* conv_b = (const float*)d_in[3];
    const float* W_xproj= (const float*)d_in[4];
    const float* W_dt   = (const float*)d_in[5];
    const float* b_dt   = (const float*)d_in[6];
    const float* A_log  = (const float*)d_in[7];
    const float* Dskip  = (const float*)d_in[8];
    const float* W_out  = (const float*)d_in[9];
    float* out = (float*)d_out;

    float *xz, *u, *xdbl, *dtb, *part;
    __nv_bfloat16 *uh3, *wxh3, *dta3, *wdt3;
    __half *xh2, *wih2, *yph2, *woh2;
    cudaGetSymbolAddress((void**)&xz,   g_xz);
    cudaGetSymbolAddress((void**)&u,    g_u);
    cudaGetSymbolAddress((void**)&xdbl, g_xdbl);
    cudaGetSymbolAddress((void**)&dtb,  g_dt);
    cudaGetSymbolAddress((void**)&part, g_part);
    cudaGetSymbolAddress((void**)&xh2,  g_xh2);
    cudaGetSymbolAddress((void**)&wih2, g_wih2);
    cudaGetSymbolAddress((void**)&uh3,  g_uh3);
    cudaGetSymbolAddress((void**)&wxh3, g_wxh3);
    cudaGetSymbolAddress((void**)&dta3, g_dta3);
    cudaGetSymbolAddress((void**)&wdt3, g_wdt3);
    cudaGetSymbolAddress((void**)&yph2, g_yph2);
    cudaGetSymbolAddress((void**)&woh2, g_woh2);

    cudaFuncSetAttribute((const void*)gemm_mma<0,0>, cudaFuncAttributeMaxDynamicSharedMemorySize, GSMEM);
    cudaFuncSetAttribute((const void*)gemm_mma<1,0>, cudaFuncAttributeMaxDynamicSharedMemorySize, GSMEM);
    cudaFuncSetAttribute((const void*)gemm_mma<0,1>, cudaFuncAttributeMaxDynamicSharedMemorySize, GSMEM);

    // --- 0) one mega split launch: all weights + x ---
    mega_split_kernel<<<(ALL_Q + 255)/256, 256>>>(
        W_in, W_xproj, W_dt, W_out, x, wih2, wxh3, wdt3, woh2, xh2);

    // --- 1) xz = x @ W_in^T (fp16 2-term: 33% less work) ---
    {
        dim3 grid((2*DMODEL)/128, MROWS/128, 1);
        gemm_mma<0,1><<<grid, 256, GSMEM>>>(xh2, wih2, xz, 2*DMODEL,
                                            2*DMODEL, K2, K2, 0, nullptr);
    }
    // --- 2) u = silu(conv(xz[:, :2048])), fused bf16x3 split ---
    {
        int total = MROWS * DMODEL / 4;
        conv_silu_split<<<(total + 255)/256, 256>>>(xz, conv_w, conv_b, u, uh3);
    }
    // --- 3) x_dbl = u @ W_xproj^T  (split-K x8, bf16x3) ---
    {
        dim3 grid(2, MROWS/128, NSPLITK);
        gemm_mma<0,0><<<grid, 256, GSMEM>>>(uh3, wxh3, part, XP_LD,
                                            XDBL_W, K3, K3/NSPLITK,
                                            (size_t)MROWS * XP_LD, nullptr);
        int tot = MROWS * XDBL_W;
        reduce_xproj<<<(tot+255)/256, 256>>>(part, xdbl, dta3);
    }
    // --- 4) dt = softplus(x_dbl[:, :128] @ W_dt^T + b_dt) (bf16x3) ---
    {
        dim3 grid(DMODEL/128, MROWS/128, 1);
        gemm_mma<1,0><<<grid, 256, GSMEM>>>(dta3, wdt3, dtb, DMODEL,
                                            DMODEL, K3DT, K3DT, 0, b_dt);
    }
    // --- 5) selective scan + gate, fused fp16 2-term split ---
    scan_kernel<<<BSZ * (DMODEL/DG), 256>>>(xdbl, dtb, u, xz, A_log, Dskip, yph2);
    // --- 6) out = ypre @ W_out^T  (fp16 2-term) ---
    {
        dim3 grid(DMODEL/128, MROWS/128, 1);
        gemm_mma<0,1><<<grid, 256, GSMEM>>>(yph2, woh2, out, DMODEL,
                                            DMODEL, K2, K2, 0, nullptr);
    }
}

// round 10
// speedup vs baseline: 1.8428x; 1.3139x over previous
#include <cuda_runtime.h>
#include <cuda_bf16.h>
#include <cuda_fp16.h>
#include <cstdint>

// ---------------- problem constants ----------------
#define DMODEL 2048
#define DSTATE 16
#define DTRANK 128
#define BSZ    2
#define SEQ    1024
#define MROWS  (BSZ*SEQ)            // 2048
#define XDBL_W (DTRANK + 2*DSTATE)  // 160
#define K3     (3*DMODEL)           // 6144 (bf16x3 expanded K)
#define K3DT   (3*DTRANK)           // 384
#define NSPLITK 8
#define XP_LD   256

// ---------------- static scratch ----------------
__device__ float g_xz  [(size_t)MROWS * (2*DMODEL)];
__device__ float g_u   [(size_t)MROWS * DMODEL];
__device__ float g_xdbl[(size_t)MROWS * XDBL_W];
__device__ float g_dt  [(size_t)MROWS * DMODEL];
__device__ float g_part[(size_t)NSPLITK * MROWS * XP_LD];

__device__ __half        g_xh1 [(size_t)MROWS  * DMODEL];      // fp16 x
__device__ __half        g_wih1[(size_t)(2*DMODEL) * DMODEL];  // fp16 W_in
__device__ __nv_bfloat16 g_uh3 [(size_t)MROWS  * K3];
__device__ __nv_bfloat16 g_wxh3[(size_t)XDBL_W * K3];
__device__ __nv_bfloat16 g_dta3[(size_t)MROWS  * K3DT];
__device__ __nv_bfloat16 g_wdt3[(size_t)DMODEL * K3DT];
__device__ __half        g_yph1[(size_t)MROWS  * DMODEL];      // fp16 ypre
__device__ __half        g_woh1[(size_t)DMODEL * DMODEL];      // fp16 W_out

// ---------------- PTX helpers ----------------
__device__ __forceinline__ uint32_t smem_u32(const void* p) {
    uint32_t a;
    asm("{ .reg .u64 t; cvta.to.shared.u64 t, %1; cvt.u32.u64 %0, t; }" : "=r"(a) : "l"(p));
    return a;
}
__device__ __forceinline__ void cp_async16(uint32_t saddr, const void* gaddr, int src_bytes) {
    asm volatile("cp.async.cg.shared.global [%0], [%1], 16, %2;"
                 :: "r"(saddr), "l"(gaddr), "r"(src_bytes) : "memory");
}
#define CP_COMMIT() asm volatile("cp.async.commit_group;" ::: "memory")
#define CP_WAIT1()  asm volatile("cp.async.wait_group 1;" ::: "memory")

__device__ __forceinline__ void ldsm_x4(uint32_t* r, uint32_t addr) {
    asm volatile("ldmatrix.sync.aligned.m8n8.x4.shared.b16 {%0,%1,%2,%3}, [%4];"
                 : "=r"(r[0]), "=r"(r[1]), "=r"(r[2]), "=r"(r[3]) : "r"(addr));
}
template<int F16>
__device__ __forceinline__ void mma16816(float* d, const uint32_t* a, const uint32_t* b) {
    if (F16)
        asm volatile(
            "mma.sync.aligned.m16n8k16.row.col.f32.f16.f16.f32 "
            "{%0,%1,%2,%3}, {%4,%5,%6,%7}, {%8,%9}, {%0,%1,%2,%3};"
            : "+f"(d[0]), "+f"(d[1]), "+f"(d[2]), "+f"(d[3])
            : "r"(a[0]), "r"(a[1]), "r"(a[2]), "r"(a[3]), "r"(b[0]), "r"(b[1]));
    else
        asm volatile(
            "mma.sync.aligned.m16n8k16.row.col.f32.bf16.bf16.f32 "
            "{%0,%1,%2,%3}, {%4,%5,%6,%7}, {%8,%9}, {%0,%1,%2,%3};"
            : "+f"(d[0]), "+f"(d[1]), "+f"(d[2]), "+f"(d[3])
            : "r"(a[0]), "r"(a[1]), "r"(a[2]), "r"(a[3]), "r"(b[0]), "r"(b[1]));
}
__device__ __forceinline__ void split2(float v, __nv_bfloat16& h, __nv_bfloat16& l) {
    h = __float2bfloat16(v);
    l = __float2bfloat16(v - __bfloat162float(h));
}
__device__ __forceinline__ uint32_t pk(__nv_bfloat16 a, __nv_bfloat16 b) {
    __nv_bfloat162 t; t.x = a; t.y = b;
    uint32_t r; *(__nv_bfloat162*)&r = t; return r;
}
__device__ __forceinline__ uint32_t pkh(__half a, __half b) {
    __half2 t; t.x = a; t.y = b;
    uint32_t r; *(__half2*)&r = t; return r;
}

// ---------------- vectorized bf16x3 split quads (B-side [hi,lo,hi]) --------
__device__ __forceinline__ void split3_b_quad(const float* __restrict__ src,
                                              int ld, int cols,
                                              __nv_bfloat16* __restrict__ dst, int q)
{
    int qpr = cols >> 3;
    int r = q / qpr;
    int c8 = (q - r * qpr) << 3;
    const float4* s = (const float4*)(src + (size_t)r * ld + c8);
    float4 v0 = s[0], v1 = s[1];
    float vv[8] = {v0.x, v0.y, v0.z, v0.w, v1.x, v1.y, v1.z, v1.w};
    __nv_bfloat16 H[8], L[8];
#pragma unroll
    for (int j = 0; j < 8; j++) split2(vv[j], H[j], L[j]);

    uint32_t w[12];
#pragma unroll
    for (int p = 0; p < 4; p++) {
        int e = 2*p, o = 2*p + 1;
        w[3*p+0] = pk(H[e], L[e]);
        w[3*p+1] = pk(H[e], H[o]);
        w[3*p+2] = pk(L[o], H[o]);
    }
    uint4* out = (uint4*)(dst + (size_t)r * 3 * cols + 3 * c8);
    out[0] = make_uint4(w[0], w[1], w[2],  w[3]);
    out[1] = make_uint4(w[4], w[5], w[6],  w[7]);
    out[2] = make_uint4(w[8], w[9], w[10], w[11]);
}

// plain fp16 quad: 8 floats -> 8 halves (one uint4)
__device__ __forceinline__ void splitf16_quad(const float* __restrict__ src,
                                              int ld, int cols,
                                              __half* __restrict__ dst, int q)
{
    int qpr = cols >> 3;
    int r = q / qpr;
    int c8 = (q - r * qpr) << 3;
    const float4* s = (const float4*)(src + (size_t)r * ld + c8);
    float4 v0 = s[0], v1 = s[1];
    float vv[8] = {v0.x, v0.y, v0.z, v0.w, v1.x, v1.y, v1.z, v1.w};
    uint32_t w[4];
#pragma unroll
    for (int p = 0; p < 4; p++)
        w[p] = pkh(__float2half_rn(vv[2*p]), __float2half_rn(vv[2*p+1]));
    *(uint4*)(dst + (size_t)r * cols + c8) = make_uint4(w[0], w[1], w[2], w[3]);
}

// ---- ONE mega split launch ----
#define WIN_Q  ((2*DMODEL)*DMODEL/8)
#define WXP_Q  (XDBL_W*DMODEL/8)
#define WDT_Q  (DMODEL*DTRANK/8)
#define WOUT_Q (DMODEL*DMODEL/8)
#define X_Q    (MROWS*DMODEL/8)
#define ALL_Q  (WIN_Q+WXP_Q+WDT_Q+WOUT_Q+X_Q)

__global__ void __launch_bounds__(256)
mega_split_kernel(const float* __restrict__ W_in,
                  const float* __restrict__ W_xproj,
                  const float* __restrict__ W_dt,
                  const float* __restrict__ W_out,
                  const float* __restrict__ x,
                  __half* __restrict__ wih1,
                  __nv_bfloat16* __restrict__ wxh3,
                  __nv_bfloat16* __restrict__ wdt3,
                  __half* __restrict__ woh1,
                  __half* __restrict__ xh1)
{
    int q = blockIdx.x * blockDim.x + threadIdx.x;
    if (q < WIN_Q)  { splitf16_quad(W_in,  DMODEL, DMODEL, wih1, q); return; }
    q -= WIN_Q;
    if (q < WXP_Q)  { split3_b_quad(W_xproj, DMODEL, DMODEL, wxh3, q); return; }
    q -= WXP_Q;
    if (q < WDT_Q)  { split3_b_quad(W_dt,  DTRANK, DTRANK, wdt3, q); return; }
    q -= WDT_Q;
    if (q < WOUT_Q) { splitf16_quad(W_out, DMODEL, DMODEL, woh1, q); return; }
    q -= WOUT_Q;
    if (q < X_Q)      splitf16_quad(x,     DMODEL, DMODEL, xh1,  q);
}

// ---------------- tensor-core GEMM: 3-stage cp.async (bf16 or fp16) --------
#define STG   32768
#define GSMEM (3*STG)

template<int EPI, int F16>
__global__ void __launch_bounds__(256, 2)
gemm_mma(const void* __restrict__ Av,
         const void* __restrict__ Bv,
         float* __restrict__ C, int ldc,
         int Nb, int Kstride, int Klen, size_t cslab,
         const float* __restrict__ bias)
{
    const __nv_bfloat16* A = (const __nv_bfloat16*)Av;  // 2-byte elements either way
    const __nv_bfloat16* B = (const __nv_bfloat16*)Bv;
    extern __shared__ __align__(1024) char smem[];
    const uint32_t sbase = smem_u32(smem);

    const int tid  = threadIdx.x;
    const int wid  = tid >> 5;
    const int lane = tid & 31;
    const int m0 = blockIdx.y << 7;
    const int n0 = blockIdx.x << 7;
    const int koff = blockIdx.z * Klen;
    C += (size_t)blockIdx.z * cslab;

    const int wm = (wid & 1) * 64;
    const int wn = (wid >> 1) * 32;
    const int nch = Klen >> 6;

    const int lrow = tid >> 3;
    const int lch  = tid & 7;
    auto load_stage = [&](uint32_t sA, int i) {
        const int k0 = koff + (i << 6);
        const uint32_t sB = sA + 16384;
#pragma unroll
        for (int j = 0; j < 4; j++) {
            int row = lrow + j * 32;
            uint32_t so = (uint32_t)(row * 128 + ((lch ^ (row & 7)) << 4));
            cp_async16(sA + so, A + (size_t)(m0 + row) * Kstride + k0 + lch * 8, 16);
            int n = n0 + row;
            int nc = (n < Nb) ? n : (Nb - 1);
            cp_async16(sB + so, B + (size_t)nc * Kstride + k0 + lch * 8,
                       (n < Nb) ? 16 : 0);
        }
    };

    float acc[4][4][4];
#pragma unroll
    for (int i = 0; i < 4; i++)
#pragma unroll
        for (int j = 0; j < 4; j++)
#pragma unroll
            for (int e = 0; e < 4; e++) acc[i][j][e] = 0.f;

    const int a_r = lane & 15;
    const int a_c = lane >> 4;
    const int b_r = ((lane >> 4) & 1) * 8 + (lane & 7);
    const int b_c = (lane >> 3) & 1;

    uint32_t buf0 = sbase, buf1 = sbase + STG, buf2 = sbase + 2*STG;

    load_stage(buf0, 0); CP_COMMIT();
    if (nch > 1) load_stage(buf1, 1);
    CP_COMMIT();

    for (int i = 0; i < nch; i++) {
        CP_WAIT1();
        __syncthreads();
        if (i + 2 < nch) load_stage(buf2, i + 2);
        CP_COMMIT();

        const uint32_t sA = buf0;
        const uint32_t sB = buf0 + 16384;
#pragma unroll
        for (int ks = 0; ks < 4; ks++) {
            uint32_t af[4][4], bf4[2][4];
#pragma unroll
            for (int mi = 0; mi < 4; mi++) {
                int row = wm + mi * 16 + a_r;
                int ch  = ks * 2 + a_c;
                ldsm_x4(af[mi], sA + row * 128 + ((ch ^ (row & 7)) << 4));
            }
#pragma unroll
            for (int nj = 0; nj < 2; nj++) {
                int row = wn + nj * 16 + b_r;
                int ch  = ks * 2 + b_c;
                ldsm_x4(bf4[nj], sB + row * 128 + ((ch ^ (row & 7)) << 4));
            }
#pragma unroll
            for (int mi = 0; mi < 4; mi++)
#pragma unroll
                for (int ni = 0; ni < 4; ni++)
                    mma16816<F16>(acc[mi][ni], af[mi], &bf4[ni >> 1][(ni & 1) * 2]);
        }
        uint32_t t = buf0; buf0 = buf1; buf1 = buf2; buf2 = t;
    }

    const int er = lane >> 2;
    const int ec = (lane & 3) * 2;
#pragma unroll
    for (int mi = 0; mi < 4; mi++) {
#pragma unroll
        for (int half = 0; half < 2; half++) {
            int m = m0 + wm + mi * 16 + er + half * 8;
            float* crow = C + (size_t)m * ldc;
#pragma unroll
            for (int ni = 0; ni < 4; ni++) {
                int n = n0 + wn + ni * 8 + ec;
                float v0 = acc[mi][ni][half * 2 + 0];
                float v1 = acc[mi][ni][half * 2 + 1];
                if (EPI == 1) {
                    v0 += bias[n];     v1 += bias[n + 1];
                    v0 = (v0 > 20.f) ? v0 : log1pf(expf(v0));
                    v1 = (v1 > 20.f) ? v1 : log1pf(expf(v1));
                }
                *(float2*)&crow[n] = make_float2(v0, v1);
            }
        }
    }
}

// ---------------- xproj split-K reduce + fused dt-rank split ----------------
__global__ void __launch_bounds__(256)
reduce_xproj(const float* __restrict__ part,
             float* __restrict__ xdbl,
             __nv_bfloat16* __restrict__ dta3)
{
    int idx = blockIdx.x * blockDim.x + threadIdx.x;
    if (idx >= MROWS * XDBL_W) return;
    int m = idx / XDBL_W;
    int n = idx - m * XDBL_W;
    float s = 0.f;
#pragma unroll
    for (int z = 0; z < NSPLITK; z++)
        s += part[(size_t)z * MROWS * XP_LD + (size_t)m * XP_LD + n];
    xdbl[idx] = s;
    if (n < DTRANK) {
        __nv_bfloat16 h, l; split2(s, h, l);
        __nv_bfloat16* o = dta3 + (size_t)m * K3DT + 3 * n;
        o[0] = h; o[1] = h; o[2] = l;
    }
}

// ---------------- conv(K=4) + SiLU + fused A-side split (4 l per thread) ---
__global__ void __launch_bounds__(256)
conv_silu_split(const float* __restrict__ xz,
                const float* __restrict__ conv_w,
                const float* __restrict__ conv_b,
                float* __restrict__ u,
                __nv_bfloat16* __restrict__ uh3)
{
    int idx = blockIdx.x * blockDim.x + threadIdx.x;
    if (idx >= MROWS * DMODEL / 4) return;
    int d = idx & (DMODEL - 1);
    int t = idx >> 11;
    int l0 = (t & 255) << 2;
    int b  = t >> 8;

    float w0 = conv_w[d*4+0], w1 = conv_w[d*4+1],
          w2 = conv_w[d*4+2], w3 = conv_w[d*4+3];
    float cb = conv_b[d];

    size_t base = (size_t)(b * SEQ) * (2*DMODEL) + d;
    float v[7];
#pragma unroll
    for (int j = 0; j < 7; j++) {
        int l = l0 - 3 + j;
        v[j] = (l >= 0) ? xz[base + (size_t)l * (2*DMODEL)] : 0.f;
    }
#pragma unroll
    for (int k = 0; k < 4; k++) {
        float acc = cb + w0*v[k] + w1*v[k+1] + w2*v[k+2] + w3*v[k+3];
        float sig = 1.f / (1.f + __expf(-acc));
        float val = acc * sig;
        int m = b * SEQ + l0 + k;
        u[(size_t)m * DMODEL + d] = val;
        __nv_bfloat16 h, lo; split2(val, h, lo);
        __nv_bfloat16* o = uh3 + (size_t)m * K3 + 3 * d;
        o[0] = h; o[1] = h; o[2] = lo;
    }
}

// ---------------- selective scan + gate + fp16 output ----------------------
#define DG 16
#define CL 64
__global__ void __launch_bounds__(256)
scan_kernel(const float* __restrict__ xdbl,
            const float* __restrict__ dt,
            const float* __restrict__ u,
            const float* __restrict__ xz,
            const float* __restrict__ A_log,
            const float* __restrict__ Dskip,
            __half* __restrict__ yph1)
{
    const int b    = blockIdx.x >> 7;
    const int dblk = blockIdx.x & 127;
    const int d0   = dblk * DG;
    const int tid  = threadIdx.x;
    const int dloc = tid >> 4;
    const int n    = tid & 15;
    const int d    = d0 + dloc;

    const float Adn = -expf(A_log[d * DSTATE + n]);
    const float Dsk = Dskip[d];
    float h = 0.f;

    __shared__ float sdt[CL*DG], su[CL*DG], sz[CL*DG];
    __shared__ float sB[CL*DSTATE], sC[CL*DSTATE];

    for (int c = 0; c < SEQ / CL; c++) {
        const int l0 = c * CL;
        __syncthreads();
#pragma unroll
        for (int e = tid; e < CL*DG; e += 256) {
            int lr = e >> 4, el = e & 15;
            size_t row = (size_t)(b * SEQ + l0 + lr);
            sdt[e] = dt[row * DMODEL + d0 + el];
            su[e]  = u [row * DMODEL + d0 + el];
            sz[e]  = xz[row * (2*DMODEL) + DMODEL + d0 + el];
            sB[e]  = xdbl[row * XDBL_W + DTRANK + el];
            sC[e]  = xdbl[row * XDBL_W + DTRANK + DSTATE + el];
        }
        __syncthreads();

#pragma unroll 8
        for (int lr = 0; lr < CL; lr++) {
            float dtv = sdt[lr*16 + dloc];
            float uu  = su [lr*16 + dloc];
            float dA  = __expf(dtv * Adn);
            h = dA * h + (dtv * uu) * sB[lr*16 + n];
            float y = h * sC[lr*16 + n];
            y += __shfl_xor_sync(0xffffffffu, y, 8, 16);
            y += __shfl_xor_sync(0xffffffffu, y, 4, 16);
            y += __shfl_xor_sync(0xffffffffu, y, 2, 16);
            y += __shfl_xor_sync(0xffffffffu, y, 1, 16);
            if (n == 0) {
                float z   = sz[lr*16 + dloc];
                float sig = 1.f / (1.f + __expf(-z));
                float val = (y + uu * Dsk) * (z * sig);
                yph1[(size_t)(b * SEQ + l0 + lr) * DMODEL + d] =
                    __float2half_rn(val);
            }
        }
    }
}

// ---------------- launch ----------------
extern "C" void kernel_launch(void* const* d_in, const int* in_sizes, int n_in,
                              void* d_out, int out_size)
{
    const float* x      = (const float*)d_in[0];
    const float* W_in   = (const float*)d_in[1];
    const float* conv_w = (const float*)d_in[2];
    const float* conv_b = (const float*)d_in[3];
    const float* W_xproj= (const float*)d_in[4];
    const float* W_dt   = (const float*)d_in[5];
    const float* b_dt   = (const float*)d_in[6];
    const float* A_log  = (const float*)d_in[7];
    const float* Dskip  = (const float*)d_in[8];
    const float* W_out  = (const float*)d_in[9];
    float* out = (float*)d_out;

    float *xz, *u, *xdbl, *dtb, *part;
    __nv_bfloat16 *uh3, *wxh3, *dta3, *wdt3;
    __half *xh1, *wih1, *yph1, *woh1;
    cudaGetSymbolAddress((void**)&xz,   g_xz);
    cudaGetSymbolAddress((void**)&u,    g_u);
    cudaGetSymbolAddress((void**)&xdbl, g_xdbl);
    cudaGetSymbolAddress((void**)&dtb,  g_dt);
    cudaGetSymbolAddress((void**)&part, g_part);
    cudaGetSymbolAddress((void**)&xh1,  g_xh1);
    cudaGetSymbolAddress((void**)&wih1, g_wih1);
    cudaGetSymbolAddress((void**)&uh3,  g_uh3);
    cudaGetSymbolAddress((void**)&wxh3, g_wxh3);
    cudaGetSymbolAddress((void**)&dta3, g_dta3);
    cudaGetSymbolAddress((void**)&wdt3, g_wdt3);
    cudaGetSymbolAddress((void**)&yph1, g_yph1);
    cudaGetSymbolAddress((void**)&woh1, g_woh1);

    cudaFuncSetAttribute((const void*)gemm_mma<0,0>, cudaFuncAttributeMaxDynamicSharedMemorySize, GSMEM);
    cudaFuncSetAttribute((const void*)gemm_mma<1,0>, cudaFuncAttributeMaxDynamicSharedMemorySize, GSMEM);
    cudaFuncSetAttribute((const void*)gemm_mma<0,1>, cudaFuncAttributeMaxDynamicSharedMemorySize, GSMEM);

    // --- 0) one mega split launch: all weights + x ---
    mega_split_kernel<<<(ALL_Q + 255)/256, 256>>>(
        W_in, W_xproj, W_dt, W_out, x, wih1, wxh3, wdt3, woh1, xh1);

    // --- 1) xz = x @ W_in^T  (plain fp16, K=2048) ---
    {
        dim3 grid((2*DMODEL)/128, MROWS/128, 1);
        gemm_mma<0,1><<<grid, 256, GSMEM>>>(xh1, wih1, xz, 2*DMODEL,
                                            2*DMODEL, DMODEL, DMODEL, 0, nullptr);
    }
    // --- 2) u = silu(conv(xz[:, :2048])), fused bf16x3 split ---
    {
        int total = MROWS * DMODEL / 4;
        conv_silu_split<<<(total + 255)/256, 256>>>(xz, conv_w, conv_b, u, uh3);
    }
    // --- 3) x_dbl = u @ W_xproj^T  (split-K x8, bf16x3) ---
    {
        dim3 grid(2, MROWS/128, NSPLITK);
        gemm_mma<0,0><<<grid, 256, GSMEM>>>(uh3, wxh3, part, XP_LD,
                                            XDBL_W, K3, K3/NSPLITK,
                                            (size_t)MROWS * XP_LD, nullptr);
        int tot = MROWS * XDBL_W;
        reduce_xproj<<<(tot+255)/256, 256>>>(part, xdbl, dta3);
    }
    // --- 4) dt = softplus(x_dbl[:, :128] @ W_dt^T + b_dt) (bf16x3) ---
    {
        dim3 grid(DMODEL/128, MROWS/128, 1);
        gemm_mma<1,0><<<grid, 256, GSMEM>>>(dta3, wdt3, dtb, DMODEL,
                                            DMODEL, K3DT, K3DT, 0, b_dt);
    }
    // --- 5) selective scan + gate, fp16 output ---
    scan_kernel<<<BSZ * (DMODEL/DG), 256>>>(xdbl, dtb, u, xz, A_log, Dskip, yph1);
    // --- 6) out = ypre @ W_out^T  (plain fp16, K=2048) ---
    {
        dim3 grid(DMODEL/128, MROWS/128, 1);
        gemm_mma<0,1><<<grid, 256, GSMEM>>>(yph1, woh1, out, DMODEL,
                                            DMODEL, DMODEL, DMODEL, 0, nullptr);
    }
}

// round 11
// speedup vs baseline: 1.9465x; 1.0563x over previous
#include <cuda_runtime.h>
#include <cuda_fp16.h>
#include <cstdint>

// ---------------- problem constants ----------------
#define DMODEL 2048
#define DSTATE 16
#define DTRANK 128
#define BSZ    2
#define SEQ    1024
#define MROWS  (BSZ*SEQ)            // 2048
#define XDBL_W (DTRANK + 2*DSTATE)  // 160
#define NSPLITK 8
#define XP_LD   256

// ---------------- static scratch ----------------
__device__ __half g_xzh [(size_t)MROWS * (2*DMODEL)];         // fp16 xz
__device__ float  g_u   [(size_t)MROWS * DMODEL];             // fp32 u (scan)
__device__ float  g_xdbl[(size_t)MROWS * XDBL_W];
__device__ float  g_dt  [(size_t)MROWS * DMODEL];
__device__ float  g_part[(size_t)NSPLITK * MROWS * XP_LD];

__device__ __half g_xh1 [(size_t)MROWS  * DMODEL];            // fp16 x
__device__ __half g_wih1[(size_t)(2*DMODEL) * DMODEL];        // fp16 W_in
__device__ __half g_uh1 [(size_t)MROWS  * DMODEL];            // fp16 u
__device__ __half g_wxh1[(size_t)XDBL_W * DMODEL];            // fp16 W_xproj
__device__ __half g_dta1[(size_t)MROWS  * DTRANK];            // fp16 dt_r
__device__ __half g_wdt1[(size_t)DMODEL * DTRANK];            // fp16 W_dt
__device__ __half g_yph1[(size_t)MROWS  * DMODEL];            // fp16 ypre
__device__ __half g_woh1[(size_t)DMODEL * DMODEL];            // fp16 W_out

// ---------------- PTX helpers ----------------
__device__ __forceinline__ uint32_t smem_u32(const void* p) {
    uint32_t a;
    asm("{ .reg .u64 t; cvta.to.shared.u64 t, %1; cvt.u32.u64 %0, t; }" : "=r"(a) : "l"(p));
    return a;
}
__device__ __forceinline__ void cp_async16(uint32_t saddr, const void* gaddr, int src_bytes) {
    asm volatile("cp.async.cg.shared.global [%0], [%1], 16, %2;"
                 :: "r"(saddr), "l"(gaddr), "r"(src_bytes) : "memory");
}
#define CP_COMMIT() asm volatile("cp.async.commit_group;" ::: "memory")
#define CP_WAIT1()  asm volatile("cp.async.wait_group 1;" ::: "memory")

__device__ __forceinline__ void ldsm_x4(uint32_t* r, uint32_t addr) {
    asm volatile("ldmatrix.sync.aligned.m8n8.x4.shared.b16 {%0,%1,%2,%3}, [%4];"
                 : "=r"(r[0]), "=r"(r[1]), "=r"(r[2]), "=r"(r[3]) : "r"(addr));
}
__device__ __forceinline__ void mma16816(float* d, const uint32_t* a, const uint32_t* b) {
    asm volatile(
        "mma.sync.aligned.m16n8k16.row.col.f32.f16.f16.f32 "
        "{%0,%1,%2,%3}, {%4,%5,%6,%7}, {%8,%9}, {%0,%1,%2,%3};"
        : "+f"(d[0]), "+f"(d[1]), "+f"(d[2]), "+f"(d[3])
        : "r"(a[0]), "r"(a[1]), "r"(a[2]), "r"(a[3]), "r"(b[0]), "r"(b[1]));
}
__device__ __forceinline__ uint32_t pkh(__half a, __half b) {
    __half2 t; t.x = a; t.y = b;
    uint32_t r; *(__half2*)&r = t; return r;
}

// plain fp16 quad: 8 floats -> 8 halves (one uint4)
__device__ __forceinline__ void splitf16_quad(const float* __restrict__ src,
                                              int ld, int cols,
                                              __half* __restrict__ dst, int q)
{
    int qpr = cols >> 3;
    int r = q / qpr;
    int c8 = (q - r * qpr) << 3;
    const float4* s = (const float4*)(src + (size_t)r * ld + c8);
    float4 v0 = s[0], v1 = s[1];
    float vv[8] = {v0.x, v0.y, v0.z, v0.w, v1.x, v1.y, v1.z, v1.w};
    uint32_t w[4];
#pragma unroll
    for (int p = 0; p < 4; p++)
        w[p] = pkh(__float2half_rn(vv[2*p]), __float2half_rn(vv[2*p+1]));
    *(uint4*)(dst + (size_t)r * cols + c8) = make_uint4(w[0], w[1], w[2], w[3]);
}

// ---- ONE mega split launch (all plain fp16) ----
#define WIN_Q  ((2*DMODEL)*DMODEL/8)
#define WXP_Q  (XDBL_W*DMODEL/8)
#define WDT_Q  (DMODEL*DTRANK/8)
#define WOUT_Q (DMODEL*DMODEL/8)
#define X_Q    (MROWS*DMODEL/8)
#define ALL_Q  (WIN_Q+WXP_Q+WDT_Q+WOUT_Q+X_Q)

__global__ void __launch_bounds__(256)
mega_split_kernel(const float* __restrict__ W_in,
                  const float* __restrict__ W_xproj,
                  const float* __restrict__ W_dt,
                  const float* __restrict__ W_out,
                  const float* __restrict__ x,
                  __half* __restrict__ wih1,
                  __half* __restrict__ wxh1,
                  __half* __restrict__ wdt1,
                  __half* __restrict__ woh1,
                  __half* __restrict__ xh1)
{
    int q = blockIdx.x * blockDim.x + threadIdx.x;
    if (q < WIN_Q)  { splitf16_quad(W_in,   DMODEL, DMODEL, wih1, q); return; }
    q -= WIN_Q;
    if (q < WXP_Q)  { splitf16_quad(W_xproj, DMODEL, DMODEL, wxh1, q); return; }
    q -= WXP_Q;
    if (q < WDT_Q)  { splitf16_quad(W_dt,   DTRANK, DTRANK, wdt1, q); return; }
    q -= WDT_Q;
    if (q < WOUT_Q) { splitf16_quad(W_out,  DMODEL, DMODEL, woh1, q); return; }
    q -= WOUT_Q;
    if (q < X_Q)      splitf16_quad(x,      DMODEL, DMODEL, xh1,  q);
}

// ---------------- fp16 tensor-core GEMM: 3-stage cp.async ------------------
// EPI==1: softplus(acc + bias[n]). OUT16: store fp16.
#define STG   32768
#define GSMEM (3*STG)

template<int EPI, int OUT16>
__global__ void __launch_bounds__(256, 2)
gemm_mma(const __half* __restrict__ A,
         const __half* __restrict__ B,
         void* __restrict__ Cv, int ldc,
         int Nb, int Kstride, int Klen, size_t cslab,
         const float* __restrict__ bias)
{
    extern __shared__ __align__(1024) char smem[];
    const uint32_t sbase = smem_u32(smem);

    const int tid  = threadIdx.x;
    const int wid  = tid >> 5;
    const int lane = tid & 31;
    const int m0 = blockIdx.y << 7;
    const int n0 = blockIdx.x << 7;
    const int koff = blockIdx.z * Klen;
    const size_t coff = (size_t)blockIdx.z * cslab;

    const int wm = (wid & 1) * 64;
    const int wn = (wid >> 1) * 32;
    const int nch = Klen >> 6;

    const int lrow = tid >> 3;
    const int lch  = tid & 7;
    auto load_stage = [&](uint32_t sA, int i) {
        const int k0 = koff + (i << 6);
        const uint32_t sB = sA + 16384;
#pragma unroll
        for (int j = 0; j < 4; j++) {
            int row = lrow + j * 32;
            uint32_t so = (uint32_t)(row * 128 + ((lch ^ (row & 7)) << 4));
            cp_async16(sA + so, A + (size_t)(m0 + row) * Kstride + k0 + lch * 8, 16);
            int n = n0 + row;
            int nc = (n < Nb) ? n : (Nb - 1);
            cp_async16(sB + so, B + (size_t)nc * Kstride + k0 + lch * 8,
                       (n < Nb) ? 16 : 0);
        }
    };

    float acc[4][4][4];
#pragma unroll
    for (int i = 0; i < 4; i++)
#pragma unroll
        for (int j = 0; j < 4; j++)
#pragma unroll
            for (int e = 0; e < 4; e++) acc[i][j][e] = 0.f;

    const int a_r = lane & 15;
    const int a_c = lane >> 4;
    const int b_r = ((lane >> 4) & 1) * 8 + (lane & 7);
    const int b_c = (lane >> 3) & 1;

    uint32_t buf0 = sbase, buf1 = sbase + STG, buf2 = sbase + 2*STG;

    load_stage(buf0, 0); CP_COMMIT();
    if (nch > 1) load_stage(buf1, 1);
    CP_COMMIT();

    for (int i = 0; i < nch; i++) {
        CP_WAIT1();
        __syncthreads();
        if (i + 2 < nch) load_stage(buf2, i + 2);
        CP_COMMIT();

        const uint32_t sA = buf0;
        const uint32_t sB = buf0 + 16384;
#pragma unroll
        for (int ks = 0; ks < 4; ks++) {
            uint32_t af[4][4], bf4[2][4];
#pragma unroll
            for (int mi = 0; mi < 4; mi++) {
                int row = wm + mi * 16 + a_r;
                int ch  = ks * 2 + a_c;
                ldsm_x4(af[mi], sA + row * 128 + ((ch ^ (row & 7)) << 4));
            }
#pragma unroll
            for (int nj = 0; nj < 2; nj++) {
                int row = wn + nj * 16 + b_r;
                int ch  = ks * 2 + b_c;
                ldsm_x4(bf4[nj], sB + row * 128 + ((ch ^ (row & 7)) << 4));
            }
#pragma unroll
            for (int mi = 0; mi < 4; mi++)
#pragma unroll
                for (int ni = 0; ni < 4; ni++)
                    mma16816(acc[mi][ni], af[mi], &bf4[ni >> 1][(ni & 1) * 2]);
        }
        uint32_t t = buf0; buf0 = buf1; buf1 = buf2; buf2 = t;
    }

    const int er = lane >> 2;
    const int ec = (lane & 3) * 2;
#pragma unroll
    for (int mi = 0; mi < 4; mi++) {
#pragma unroll
        for (int half = 0; half < 2; half++) {
            int m = m0 + wm + mi * 16 + er + half * 8;
#pragma unroll
            for (int ni = 0; ni < 4; ni++) {
                int n = n0 + wn + ni * 8 + ec;
                float v0 = acc[mi][ni][half * 2 + 0];
                float v1 = acc[mi][ni][half * 2 + 1];
                if (EPI == 1) {
                    v0 += bias[n];     v1 += bias[n + 1];
                    v0 = (v0 > 20.f) ? v0 : log1pf(expf(v0));
                    v1 = (v1 > 20.f) ? v1 : log1pf(expf(v1));
                }
                if (OUT16) {
                    __half* crow = (__half*)Cv + coff + (size_t)m * ldc;
                    *(uint32_t*)&crow[n] =
                        pkh(__float2half_rn(v0), __float2half_rn(v1));
                } else {
                    float* crow = (float*)Cv + coff + (size_t)m * ldc;
                    *(float2*)&crow[n] = make_float2(v0, v1);
                }
            }
        }
    }
}

// ---------------- xproj split-K reduce + fused fp16 dt-rank ----------------
__global__ void __launch_bounds__(256)
reduce_xproj(const float* __restrict__ part,
             float* __restrict__ xdbl,
             __half* __restrict__ dta1)
{
    int idx = blockIdx.x * blockDim.x + threadIdx.x;
    if (idx >= MROWS * XDBL_W) return;
    int m = idx / XDBL_W;
    int n = idx - m * XDBL_W;
    float s = 0.f;
#pragma unroll
    for (int z = 0; z < NSPLITK; z++)
        s += part[(size_t)z * MROWS * XP_LD + (size_t)m * XP_LD + n];
    xdbl[idx] = s;
    if (n < DTRANK)
        dta1[(size_t)m * DTRANK + n] = __float2half_rn(s);
}

// ---------------- conv(K=4) + SiLU, fp16 in, fp32 + fp16 out --------------
__global__ void __launch_bounds__(256)
conv_silu_split(const __half* __restrict__ xzh,
                const float* __restrict__ conv_w,
                const float* __restrict__ conv_b,
                float* __restrict__ u,
                __half* __restrict__ uh1)
{
    int idx = blockIdx.x * blockDim.x + threadIdx.x;
    if (idx >= MROWS * DMODEL / 4) return;
    int d = idx & (DMODEL - 1);
    int t = idx >> 11;
    int l0 = (t & 255) << 2;
    int b  = t >> 8;

    float w0 = conv_w[d*4+0], w1 = conv_w[d*4+1],
          w2 = conv_w[d*4+2], w3 = conv_w[d*4+3];
    float cb = conv_b[d];

    size_t base = (size_t)(b * SEQ) * (2*DMODEL) + d;
    float v[7];
#pragma unroll
    for (int j = 0; j < 7; j++) {
        int l = l0 - 3 + j;
        v[j] = (l >= 0) ? __half2float(xzh[base + (size_t)l * (2*DMODEL)]) : 0.f;
    }
#pragma unroll
    for (int k = 0; k < 4; k++) {
        float acc = cb + w0*v[k] + w1*v[k+1] + w2*v[k+2] + w3*v[k+3];
        float sig = 1.f / (1.f + __expf(-acc));
        float val = acc * sig;
        int m = b * SEQ + l0 + k;
        u[(size_t)m * DMODEL + d] = val;
        uh1[(size_t)m * DMODEL + d] = __float2half_rn(val);
    }
}

// ---------------- selective scan + gate + fp16 output ----------------------
#define DG 16
#define CL 64
__global__ void __launch_bounds__(256)
scan_kernel(const float* __restrict__ xdbl,
            const float* __restrict__ dt,
            const float* __restrict__ u,
            const __half* __restrict__ xzh,
            const float* __restrict__ A_log,
            const float* __restrict__ Dskip,
            __half* __restrict__ yph1)
{
    const int b    = blockIdx.x >> 7;
    const int dblk = blockIdx.x & 127;
    const int d0   = dblk * DG;
    const int tid  = threadIdx.x;
    const int dloc = tid >> 4;
    const int n    = tid & 15;
    const int d    = d0 + dloc;

    const float Adn = -expf(A_log[d * DSTATE + n]);
    const float Dsk = Dskip[d];
    float h = 0.f;

    __shared__ float sdt[CL*DG], su[CL*DG], sz[CL*DG];
    __shared__ float sB[CL*DSTATE], sC[CL*DSTATE];

    for (int c = 0; c < SEQ / CL; c++) {
        const int l0 = c * CL;
        __syncthreads();
#pragma unroll
        for (int e = tid; e < CL*DG; e += 256) {
            int lr = e >> 4, el = e & 15;
            size_t row = (size_t)(b * SEQ + l0 + lr);
            sdt[e] = dt[row * DMODEL + d0 + el];
            su[e]  = u [row * DMODEL + d0 + el];
            sz[e]  = __half2float(xzh[row * (2*DMODEL) + DMODEL + d0 + el]);
            sB[e]  = xdbl[row * XDBL_W + DTRANK + el];
            sC[e]  = xdbl[row * XDBL_W + DTRANK + DSTATE + el];
        }
        __syncthreads();

#pragma unroll 8
        for (int lr = 0; lr < CL; lr++) {
            float dtv = sdt[lr*16 + dloc];
            float uu  = su [lr*16 + dloc];
            float dA  = __expf(dtv * Adn);
            h = dA * h + (dtv * uu) * sB[lr*16 + n];
            float y = h * sC[lr*16 + n];
            y += __shfl_xor_sync(0xffffffffu, y, 8, 16);
            y += __shfl_xor_sync(0xffffffffu, y, 4, 16);
            y += __shfl_xor_sync(0xffffffffu, y, 2, 16);
            y += __shfl_xor_sync(0xffffffffu, y, 1, 16);
            if (n == 0) {
                float z   = sz[lr*16 + dloc];
                float sig = 1.f / (1.f + __expf(-z));
                float val = (y + uu * Dsk) * (z * sig);
                yph1[(size_t)(b * SEQ + l0 + lr) * DMODEL + d] =
                    __float2half_rn(val);
            }
        }
    }
}

// ---------------- launch ----------------
extern "C" void kernel_launch(void* const* d_in, const int* in_sizes, int n_in,
                              void* d_out, int out_size)
{
    const float* x      = (const float*)d_in[0];
    const float* W_in   = (const float*)d_in[1];
    const float* conv_w = (const float*)d_in[2];
    const float* conv_b = (const float*)d_in[3];
    const float* W_xproj= (const float*)d_in[4];
    const float* W_dt   = (const float*)d_in[5];
    const float* b_dt   = (const float*)d_in[6];
    const float* A_log  = (const float*)d_in[7];
    const float* Dskip  = (const float*)d_in[8];
    const float* W_out  = (const float*)d_in[9];
    float* out = (float*)d_out;

    float *u, *xdbl, *dtb, *part;
    __half *xzh, *xh1, *wih1, *uh1, *wxh1, *dta1, *wdt1, *yph1, *woh1;
    cudaGetSymbolAddress((void**)&xzh,  g_xzh);
    cudaGetSymbolAddress((void**)&u,    g_u);
    cudaGetSymbolAddress((void**)&xdbl, g_xdbl);
    cudaGetSymbolAddress((void**)&dtb,  g_dt);
    cudaGetSymbolAddress((void**)&part, g_part);
    cudaGetSymbolAddress((void**)&xh1,  g_xh1);
    cudaGetSymbolAddress((void**)&wih1, g_wih1);
    cudaGetSymbolAddress((void**)&uh1,  g_uh1);
    cudaGetSymbolAddress((void**)&wxh1, g_wxh1);
    cudaGetSymbolAddress((void**)&dta1, g_dta1);
    cudaGetSymbolAddress((void**)&wdt1, g_wdt1);
    cudaGetSymbolAddress((void**)&yph1, g_yph1);
    cudaGetSymbolAddress((void**)&woh1, g_woh1);

    cudaFuncSetAttribute((const void*)gemm_mma<0,0>, cudaFuncAttributeMaxDynamicSharedMemorySize, GSMEM);
    cudaFuncSetAttribute((const void*)gemm_mma<1,0>, cudaFuncAttributeMaxDynamicSharedMemorySize, GSMEM);
    cudaFuncSetAttribute((const void*)gemm_mma<0,1>, cudaFuncAttributeMaxDynamicSharedMemorySize, GSMEM);

    // --- 0) one mega split launch: all weights + x (plain fp16) ---
    mega_split_kernel<<<(ALL_Q + 255)/256, 256>>>(
        W_in, W_xproj, W_dt, W_out, x, wih1, wxh1, wdt1, woh1, xh1);

    // --- 1) xz = x @ W_in^T  (fp16, K=2048, fp16 output) ---
    {
        dim3 grid((2*DMODEL)/128, MROWS/128, 1);
        gemm_mma<0,1><<<grid, 256, GSMEM>>>(xh1, wih1, xzh, 2*DMODEL,
                                            2*DMODEL, DMODEL, DMODEL, 0, nullptr);
    }
    // --- 2) u = silu(conv(xz[:, :2048])) -> fp32 u + fp16 uh1 ---
    {
        int total = MROWS * DMODEL / 4;
        conv_silu_split<<<(total + 255)/256, 256>>>(xzh, conv_w, conv_b, u, uh1);
    }
    // --- 3) x_dbl = u @ W_xproj^T  (fp16, split-K x8) ---
    {
        dim3 grid(2, MROWS/128, NSPLITK);
        gemm_mma<0,0><<<grid, 256, GSMEM>>>(uh1, wxh1, part, XP_LD,
                                            XDBL_W, DMODEL, DMODEL/NSPLITK,
                                            (size_t)MROWS * XP_LD, nullptr);
        int tot = MROWS * XDBL_W;
        reduce_xproj<<<(tot+255)/256, 256>>>(part, xdbl, dta1);
    }
    // --- 4) dt = softplus(x_dbl[:, :128] @ W_dt^T + b_dt) (fp16, K=128) ---
    {
        dim3 grid(DMODEL/128, MROWS/128, 1);
        gemm_mma<1,0><<<grid, 256, GSMEM>>>(dta1, wdt1, dtb, DMODEL,
                                            DMODEL, DTRANK, DTRANK, 0, b_dt);
    }
    // --- 5) selective scan + gate, fp16 output ---
    scan_kernel<<<BSZ * (DMODEL/DG), 256>>>(xdbl, dtb, u, xzh, A_log, Dskip, yph1);
    // --- 6) out = ypre @ W_out^T  (fp16, K=2048, fp32 output) ---
    {
        dim3 grid(DMODEL/128, MROWS/128, 1);
        gemm_mma<0,0><<<grid, 256, GSMEM>>>(yph1, woh1, out, DMODEL,
                                            DMODEL, DMODEL, DMODEL, 0, nullptr);
    }
}